// round 7
// baseline (speedup 1.0000x reference)
#include <cuda_runtime.h>
#include <cuda_bf16.h>
#include <cstdint>

// y[b,o] = sum_{i,d} P_d(tanh(x[b,i])) * coeffs[i,o,d]
// GEMM M=4096 N=1024 K=8192. v7: precompute split-bf16 A and B into __device__
// globals (2 prep kernels), then a pure 3-pass bf16 mma.sync GEMM with a
// 3-stage cp.async pipeline. Hot loop: cp.async + ldmatrix + HMMA only.

#define BATCH   4096
#define IN_DIM  1024
#define OUT_DIM 1024
#define NB      8
#define KTOT    (IN_DIM * NB)   // 8192

#define BM 128
#define BN 256
#define KK 32                   // k per iter
#define NIT (KTOT / KK)         // 256
#define THREADS 512             // 16 warps, 4(M) x 4(N), warp tile 32x64

#define A_LD 40                 // bf16/row (80B stride, conflict-free)
#define B_LD 40
#define ST_AH 0
#define ST_AL 10240             // 128*80
#define ST_BH 20480
#define ST_BL 40960             // +256*80
#define STAGE_BYTES 61440
#define STAGES 3
#define SMEM_DYN (STAGES * STAGE_BYTES)   // 184320

// Precomputed split operands
__device__ __nv_bfloat16 gAh[(size_t)BATCH * KTOT];
__device__ __nv_bfloat16 gAl[(size_t)BATCH * KTOT];
__device__ __nv_bfloat16 gBh[(size_t)OUT_DIM * KTOT];
__device__ __nv_bfloat16 gBl[(size_t)OUT_DIM * KTOT];

__device__ __forceinline__ uint32_t bf2u(__nv_bfloat162 v) {
    return *reinterpret_cast<uint32_t*>(&v);
}
__device__ __forceinline__ void ldx4(uint32_t* r, uint32_t addr) {
    asm volatile("ldmatrix.sync.aligned.m8n8.x4.shared.b16 {%0,%1,%2,%3}, [%4];"
                 : "=r"(r[0]), "=r"(r[1]), "=r"(r[2]), "=r"(r[3]) : "r"(addr));
}
__device__ __forceinline__ void mma16816(float* d, const uint32_t* a, uint32_t b0, uint32_t b1) {
    asm volatile("mma.sync.aligned.m16n8k16.row.col.f32.bf16.bf16.f32 "
                 "{%0,%1,%2,%3}, {%4,%5,%6,%7}, {%8,%9}, {%0,%1,%2,%3};"
                 : "+f"(d[0]), "+f"(d[1]), "+f"(d[2]), "+f"(d[3])
                 : "r"(a[0]), "r"(a[1]), "r"(a[2]), "r"(a[3]), "r"(b0), "r"(b1));
}
__device__ __forceinline__ void cpa16(uint32_t dst, const void* src) {
    asm volatile("cp.async.cg.shared.global [%0], [%1], 16;" :: "r"(dst), "l"(src));
}

// split 4 floats into bf16 hi pair-words and lo pair-words
__device__ __forceinline__ void split4(const float* v, uint32_t& h, uint32_t& h2,
                                       uint32_t& l, uint32_t& l2) {
    __nv_bfloat162 h01 = __floats2bfloat162_rn(v[0], v[1]);
    __nv_bfloat162 h23 = __floats2bfloat162_rn(v[2], v[3]);
    __nv_bfloat162 l01 = __floats2bfloat162_rn(v[0] - __bfloat162float(h01.x),
                                               v[1] - __bfloat162float(h01.y));
    __nv_bfloat162 l23 = __floats2bfloat162_rn(v[2] - __bfloat162float(h23.x),
                                               v[3] - __bfloat162float(h23.y));
    h = bf2u(h01); h2 = bf2u(h23); l = bf2u(l01); l2 = bf2u(l23);
}

// ---- prep kernel A: tanh + recurrence + split -> gAh/gAl [m][k] ----
__global__ __launch_bounds__(256)
void prep_a_kernel(const float* __restrict__ x,
                   const float* __restrict__ a_ptr,
                   const float* __restrict__ q_ptr) {
    int g = blockIdx.x * 256 + threadIdx.x;      // 0 .. 4194303
    int m = g >> 10;
    int i = g & 1023;
    const float a = a_ptr[0];
    const float q = q_ptr[0];
    float xt = tanhf(x[(size_t)m * IN_DIM + i]);
    float p[NB];
    p[0] = 1.0f;
    p[1] = xt - a;
    float qn = q;
#pragma unroll
    for (int n = 2; n < NB; n++) {
        float qn1 = qn * q;
        p[n] = (xt - (a + qn1)) * p[n - 1] - (a * qn) * p[n - 2];
        qn = qn1;
    }
    uint4 H, L;
    split4(p,     H.x, H.y, L.x, L.y);
    split4(p + 4, H.z, H.w, L.z, L.w);
    size_t off = (size_t)m * KTOT + (size_t)i * NB;
    *reinterpret_cast<uint4*>(&gAh[off]) = H;
    *reinterpret_cast<uint4*>(&gAl[off]) = L;
}

// ---- prep kernel B: split coeffs -> gBh/gBl [o][k], k = i*8+d ----
__global__ __launch_bounds__(256)
void prep_b_kernel(const float* __restrict__ coeffs) {
    int g = blockIdx.x * 256 + threadIdx.x;      // 0 .. 1048575
    int o = g >> 10;
    int i = g & 1023;
    const float* src = coeffs + ((size_t)i * OUT_DIM + o) * NB;
    float4 v0 = *reinterpret_cast<const float4*>(src);
    float4 v1 = *reinterpret_cast<const float4*>(src + 4);
    float v[8] = {v0.x, v0.y, v0.z, v0.w, v1.x, v1.y, v1.z, v1.w};
    uint4 H, L;
    split4(v,     H.x, H.y, L.x, L.y);
    split4(v + 4, H.z, H.w, L.z, L.w);
    size_t off = (size_t)o * KTOT + (size_t)i * NB;
    *reinterpret_cast<uint4*>(&gBh[off]) = H;
    *reinterpret_cast<uint4*>(&gBl[off]) = L;
}

// ---- main GEMM ----
__global__ __launch_bounds__(THREADS, 1)
void kan_mma4_kernel(float* __restrict__ y) {
    extern __shared__ __align__(16) char sm[];
    const uint32_t sbase = (uint32_t)__cvta_generic_to_shared(sm);

    const int bn0 = blockIdx.x * BN;
    const int bm0 = blockIdx.y * BM;
    const int tid = threadIdx.x;
    const int lane = tid & 31;
    const int warp = tid >> 5;
    const int wm = warp >> 2;
    const int wn = warp & 3;

    float acc[2][8][4];
#pragma unroll
    for (int mi = 0; mi < 2; mi++)
#pragma unroll
        for (int nb = 0; nb < 8; nb++)
#pragma unroll
            for (int r = 0; r < 4; r++) acc[mi][nb][r] = 0.0f;

    // ldmatrix lane offsets (same proven layout as v6)
    const int aRow = wm * 32 + (lane & 15);
    const uint32_t aOff = (uint32_t)(aRow * A_LD + (lane >> 4) * 8) * 2u;
    const int bRow = wn * 64 + ((lane >> 4) << 3) + (lane & 7);
    const uint32_t bOff = (uint32_t)(bRow * B_LD + ((lane >> 3) & 1) * 8) * 2u;

    // per-thread cp.async coordinates (constant across iters)
    // A: 2 chunks (h/l x 512): c = tid + jj*512
    int aHalf[2], aRowC[2], aJ[2];
#pragma unroll
    for (int jj = 0; jj < 2; jj++) {
        int c = tid + jj * THREADS;
        aHalf[jj] = c >> 9;
        int r = c & 511;
        aRowC[jj] = r >> 2;
        aJ[jj] = r & 3;
    }
    // B: 4 chunks: c = tid + jj*512
    int bHalf[4], bRowC[4], bJ[4];
#pragma unroll
    for (int jj = 0; jj < 4; jj++) {
        int c = tid + jj * THREADS;
        bHalf[jj] = c >> 10;
        int r = c & 1023;
        bRowC[jj] = r >> 2;
        bJ[jj] = r & 3;
    }

    auto loadStage = [&](int s, int it) {
        const uint32_t st = sbase + (uint32_t)s * STAGE_BYTES;
        const int k0 = it * KK;   // element offset along k
#pragma unroll
        for (int jj = 0; jj < 2; jj++) {
            const __nv_bfloat16* src =
                (aHalf[jj] ? gAl : gAh) + (size_t)(bm0 + aRowC[jj]) * KTOT + k0 + aJ[jj] * 8;
            uint32_t dst = st + (aHalf[jj] ? ST_AL : ST_AH) + aRowC[jj] * (A_LD * 2) + aJ[jj] * 16;
            cpa16(dst, src);
        }
#pragma unroll
        for (int jj = 0; jj < 4; jj++) {
            const __nv_bfloat16* src =
                (bHalf[jj] ? gBl : gBh) + (size_t)(bn0 + bRowC[jj]) * KTOT + k0 + bJ[jj] * 8;
            uint32_t dst = st + (bHalf[jj] ? ST_BL : ST_BH) + bRowC[jj] * (B_LD * 2) + bJ[jj] * 16;
            cpa16(dst, src);
        }
        asm volatile("cp.async.commit_group;" ::: "memory");
    };

    auto compute = [&](int s) {
        const uint32_t st = sbase + (uint32_t)s * STAGE_BYTES;
        const uint32_t pAh = st + ST_AH;
        const uint32_t pAl = st + ST_AL;
        const uint32_t pBh = st + ST_BH;
        const uint32_t pBl = st + ST_BL;
#pragma unroll
        for (int ks = 0; ks < 2; ks++) {
            const uint32_t kb = (uint32_t)ks * 32u;
            uint32_t ah[2][4], al[2][4];
#pragma unroll
            for (int mi = 0; mi < 2; mi++)
                ldx4(ah[mi], pAh + aOff + kb + (uint32_t)mi * (16 * A_LD * 2));
#pragma unroll
            for (int mi = 0; mi < 2; mi++)
                ldx4(al[mi], pAl + aOff + kb + (uint32_t)mi * (16 * A_LD * 2));
#pragma unroll
            for (int ng = 0; ng < 4; ng++) {
                uint32_t bh[4], bl[4];
                ldx4(bh, pBh + bOff + kb + (uint32_t)ng * (16 * B_LD * 2));
                ldx4(bl, pBl + bOff + kb + (uint32_t)ng * (16 * B_LD * 2));
#pragma unroll
                for (int mi = 0; mi < 2; mi++) {
                    mma16816(acc[mi][2 * ng],     ah[mi], bh[0], bh[1]);
                    mma16816(acc[mi][2 * ng + 1], ah[mi], bh[2], bh[3]);
                }
#pragma unroll
                for (int mi = 0; mi < 2; mi++) {
                    mma16816(acc[mi][2 * ng],     ah[mi], bl[0], bl[1]);
                    mma16816(acc[mi][2 * ng + 1], ah[mi], bl[2], bl[3]);
                }
#pragma unroll
                for (int mi = 0; mi < 2; mi++) {
                    mma16816(acc[mi][2 * ng],     al[mi], bh[0], bh[1]);
                    mma16816(acc[mi][2 * ng + 1], al[mi], bh[2], bh[3]);
                }
            }
        }
    };

    // ---- 3-stage pipeline: preload 2, then {wait g(it); sync; issue g(it+2); compute} ----
    loadStage(0, 0);
    loadStage(1, 1);

    for (int it = 0; it < NIT; ++it) {
        if (it + 1 < NIT) {
            asm volatile("cp.async.wait_group 1;" ::: "memory");
        } else {
            asm volatile("cp.async.wait_group 0;" ::: "memory");
        }
        __syncthreads();
        if (it + 2 < NIT) loadStage((it + 2) % STAGES, it + 2);
        compute(it % STAGES);
    }

    // ---- epilogue ----
#pragma unroll
    for (int mi = 0; mi < 2; mi++) {
#pragma unroll
        for (int nb = 0; nb < 8; nb++) {
            int r = bm0 + wm * 32 + mi * 16 + (lane >> 2);
            int c = bn0 + wn * 64 + nb * 8 + (lane & 3) * 2;
            *reinterpret_cast<float2*>(y + (size_t)r * OUT_DIM + c) =
                make_float2(acc[mi][nb][0], acc[mi][nb][1]);
            *reinterpret_cast<float2*>(y + (size_t)(r + 8) * OUT_DIM + c) =
                make_float2(acc[mi][nb][2], acc[mi][nb][3]);
        }
    }
}

extern "C" void kernel_launch(void* const* d_in, const int* in_sizes, int n_in,
                              void* d_out, int out_size) {
    const float* x      = (const float*)d_in[0];
    const float* a_ptr  = (const float*)d_in[1];
    const float* q_ptr  = (const float*)d_in[2];
    const float* coeffs = (const float*)d_in[3];
    float* y = (float*)d_out;

    prep_b_kernel<<<(OUT_DIM * IN_DIM) / 256, 256>>>(coeffs);
    prep_a_kernel<<<(BATCH * IN_DIM) / 256, 256>>>(x, a_ptr, q_ptr);

    cudaFuncSetAttribute(kan_mma4_kernel, cudaFuncAttributeMaxDynamicSharedMemorySize, SMEM_DYN);
    dim3 grid(OUT_DIM / BN, BATCH / BM);  // (4, 32) = 128 CTAs, single wave
    kan_mma4_kernel<<<grid, THREADS, SMEM_DYN>>>(y);
}

// round 9
// speedup vs baseline: 1.1772x; 1.1772x over previous
#include <cuda_runtime.h>
#include <cuda_bf16.h>
#include <cstdint>

// y[b,o] = sum_{i,d} P_d(tanh(x[b,i])) * coeffs[i,o,d]
// GEMM M=4096 N=1024 K=8192, A generated on the fly (fused, v6 base).
// mma.sync m16n8k16 bf16, split-bf16 3-pass, fp32 accum.
// v9 (= v8 resubmit; round-8 bench was an infra failure):
// software-pipelined B fragments + staged A-fragment loads inside compute()
// to eliminate the per-ks LDSM burst that was draining the tensor pipe.

#define BATCH   4096
#define IN_DIM  1024
#define OUT_DIM 1024
#define NB      8

#define BM 128
#define BN 256
#define BKI 4                  // i-values per iter
#define NIT (IN_DIM / BKI)     // 256
#define THREADS 512            // 16 warps, 4(M) x 4(N), warp tile 32x64

#define A_LD 40                // bf16 per row (80B stride, conflict-free)
#define B_LD 40
#define A_BYTES (BM * A_LD * 2)                // 10240
#define B_BYTES (BN * B_LD * 2)                // 20480
#define BUF_BYTES (2 * A_BYTES + 2 * B_BYTES)  // 61440
#define SMEM_DYN (2 * BUF_BYTES)               // 122880

__device__ __forceinline__ void ldx4(uint32_t* r, uint32_t addr) {
    asm volatile("ldmatrix.sync.aligned.m8n8.x4.shared.b16 {%0,%1,%2,%3}, [%4];"
                 : "=r"(r[0]), "=r"(r[1]), "=r"(r[2]), "=r"(r[3]) : "r"(addr));
}
__device__ __forceinline__ void mma16816(float* d, const uint32_t* a, uint32_t b0, uint32_t b1) {
    asm volatile("mma.sync.aligned.m16n8k16.row.col.f32.bf16.bf16.f32 "
                 "{%0,%1,%2,%3}, {%4,%5,%6,%7}, {%8,%9}, {%0,%1,%2,%3};"
                 : "+f"(d[0]), "+f"(d[1]), "+f"(d[2]), "+f"(d[3])
                 : "r"(a[0]), "r"(a[1]), "r"(a[2]), "r"(a[3]), "r"(b0), "r"(b1));
}
__device__ __forceinline__ uint32_t bf2u(__nv_bfloat162 v) {
    return *reinterpret_cast<uint32_t*>(&v);
}

__global__ __launch_bounds__(THREADS, 1)
void kan_mma5_kernel(const float* __restrict__ x,
                     const float* __restrict__ a_ptr,
                     const float* __restrict__ q_ptr,
                     const float* __restrict__ coeffs,
                     float* __restrict__ y) {
    extern __shared__ __align__(16) char sm[];
    const uint32_t sbase = (uint32_t)__cvta_generic_to_shared(sm);

    const float a = a_ptr[0];
    const float q = q_ptr[0];
    const int bn0 = blockIdx.x * BN;
    const int bm0 = blockIdx.y * BM;
    const int tid = threadIdx.x;
    const int lane = tid & 31;
    const int warp = tid >> 5;
    const int wm = warp >> 2;   // 0..3
    const int wn = warp & 3;    // 0..3

    float acc[2][8][4];
#pragma unroll
    for (int mi = 0; mi < 2; mi++)
#pragma unroll
        for (int nb = 0; nb < 8; nb++)
#pragma unroll
            for (int r = 0; r < 4; r++) acc[mi][nb][r] = 0.0f;

    const int aRow = wm * 32 + (lane & 15);
    const uint32_t aOff = (uint32_t)(aRow * A_LD + (lane >> 4) * 8) * 2u;
    const int bRow = wn * 64 + ((lane >> 4) << 3) + (lane & 7);
    const uint32_t bOff = (uint32_t)(bRow * B_LD + ((lane >> 3) & 1) * 8) * 2u;

    float4 pfB[4];
    float pfX;

    auto loadG = [&](int i0) {
#pragma unroll
        for (int jj = 0; jj < 4; jj++) {
            int t = tid + jj * THREADS;
            int il = t >> 9;
            int f = t & 511;
            int n = f >> 1;
            int dh = f & 1;
            pfB[jj] = *reinterpret_cast<const float4*>(
                coeffs + (size_t)(i0 + il) * (OUT_DIM * NB) + (size_t)(bn0 + n) * NB + dh * 4);
        }
        {
            int il = tid & 3;
            int row = tid >> 2;
            pfX = x[(size_t)(bm0 + row) * IN_DIM + i0 + il];
        }
    };

    auto storeS = [&](int buf) {
        char* const base = sm + buf * BUF_BYTES;
        char* const Ah = base;
        char* const Al = base + A_BYTES;
        char* const Bh = base + 2 * A_BYTES;
        char* const Bl = base + 2 * A_BYTES + B_BYTES;

#pragma unroll
        for (int jj = 0; jj < 4; jj++) {
            int t = tid + jj * THREADS;
            int il = t >> 9;
            int f = t & 511;
            int n = f >> 1;
            int dh = f & 1;
            float v[4] = {pfB[jj].x, pfB[jj].y, pfB[jj].z, pfB[jj].w};
            __nv_bfloat162 h01 = __floats2bfloat162_rn(v[0], v[1]);
            __nv_bfloat162 h23 = __floats2bfloat162_rn(v[2], v[3]);
            __nv_bfloat162 l01 = __floats2bfloat162_rn(v[0] - __bfloat162float(h01.x),
                                                       v[1] - __bfloat162float(h01.y));
            __nv_bfloat162 l23 = __floats2bfloat162_rn(v[2] - __bfloat162float(h23.x),
                                                       v[3] - __bfloat162float(h23.y));
            uint32_t off = (uint32_t)(n * B_LD + il * 8 + dh * 4) * 2u;
            *reinterpret_cast<uint2*>(Bh + off) = make_uint2(bf2u(h01), bf2u(h23));
            *reinterpret_cast<uint2*>(Bl + off) = make_uint2(bf2u(l01), bf2u(l23));
        }
        {
            int il = tid & 3;
            int row = tid >> 2;
            float xt = tanhf(pfX);
            float p[NB];
            p[0] = 1.0f;
            p[1] = xt - a;
            float qn = q;
#pragma unroll
            for (int n = 2; n < NB; n++) {
                float qn1 = qn * q;
                p[n] = (xt - (a + qn1)) * p[n - 1] - (a * qn) * p[n - 2];
                qn = qn1;
            }
            uint32_t hw[4], lw[4];
#pragma unroll
            for (int j = 0; j < 4; j++) {
                __nv_bfloat162 h = __floats2bfloat162_rn(p[2 * j], p[2 * j + 1]);
                __nv_bfloat162 l = __floats2bfloat162_rn(p[2 * j]     - __bfloat162float(h.x),
                                                         p[2 * j + 1] - __bfloat162float(h.y));
                hw[j] = bf2u(h);
                lw[j] = bf2u(l);
            }
            uint32_t off = (uint32_t)(row * A_LD + il * 8) * 2u;
            *reinterpret_cast<uint4*>(Ah + off) = make_uint4(hw[0], hw[1], hw[2], hw[3]);
            *reinterpret_cast<uint4*>(Al + off) = make_uint4(lw[0], lw[1], lw[2], lw[3]);
        }
    };

    auto compute = [&](int buf) {
        const uint32_t base = sbase + (uint32_t)buf * BUF_BYTES;
        const uint32_t pAh = base;
        const uint32_t pAl = base + A_BYTES;
        const uint32_t pBh = base + 2 * A_BYTES;
        const uint32_t pBl = base + 2 * A_BYTES + B_BYTES;
#pragma unroll
        for (int ks = 0; ks < 2; ks++) {
            const uint32_t kb = (uint32_t)ks * 32u;
            uint32_t ah[2][4], al[2][4];
            uint32_t bch[4], bcl[4], bnh[4], bnl[4];
            // head: minimal loads before first HMMA (ah + b(ng0)); al deferred
            ldx4(ah[0], pAh + aOff + kb);
            ldx4(ah[1], pAh + aOff + kb + (16 * A_LD * 2));
            ldx4(bch, pBh + bOff + kb);
            ldx4(bcl, pBl + bOff + kb);
            ldx4(al[0], pAl + aOff + kb);
            ldx4(al[1], pAl + aOff + kb + (16 * A_LD * 2));
#pragma unroll
            for (int ng = 0; ng < 4; ng++) {
                // prefetch next ng's B fragments under this ng's HMMAs
                if (ng < 3) {
                    ldx4(bnh, pBh + bOff + kb + (uint32_t)(ng + 1) * (16 * B_LD * 2));
                    ldx4(bnl, pBl + bOff + kb + (uint32_t)(ng + 1) * (16 * B_LD * 2));
                }
                // pass 1: Ah*Bh
#pragma unroll
                for (int mi = 0; mi < 2; mi++) {
                    mma16816(acc[mi][2 * ng],     ah[mi], bch[0], bch[1]);
                    mma16816(acc[mi][2 * ng + 1], ah[mi], bch[2], bch[3]);
                }
                // pass 2: Ah*Bl
#pragma unroll
                for (int mi = 0; mi < 2; mi++) {
                    mma16816(acc[mi][2 * ng],     ah[mi], bcl[0], bcl[1]);
                    mma16816(acc[mi][2 * ng + 1], ah[mi], bcl[2], bcl[3]);
                }
                // pass 3: Al*Bh
#pragma unroll
                for (int mi = 0; mi < 2; mi++) {
                    mma16816(acc[mi][2 * ng],     al[mi], bch[0], bch[1]);
                    mma16816(acc[mi][2 * ng + 1], al[mi], bch[2], bch[3]);
                }
                if (ng < 3) {
#pragma unroll
                    for (int t = 0; t < 4; t++) { bch[t] = bnh[t]; bcl[t] = bnl[t]; }
                }
            }
        }
    };

    // ---- pipeline ----
    loadG(0);
    storeS(0);
    loadG(BKI);
    __syncthreads();

    for (int it = 0; it < NIT; ++it) {
        compute(it & 1);
        if (it + 1 < NIT) {
            storeS((it + 1) & 1);
            if (it + 2 < NIT) loadG((it + 2) * BKI);
            __syncthreads();
        }
    }

    // ---- epilogue ----
#pragma unroll
    for (int mi = 0; mi < 2; mi++) {
#pragma unroll
        for (int nb = 0; nb < 8; nb++) {
            int r = bm0 + wm * 32 + mi * 16 + (lane >> 2);
            int c = bn0 + wn * 64 + nb * 8 + (lane & 3) * 2;
            *reinterpret_cast<float2*>(y + (size_t)r * OUT_DIM + c) =
                make_float2(acc[mi][nb][0], acc[mi][nb][1]);
            *reinterpret_cast<float2*>(y + (size_t)(r + 8) * OUT_DIM + c) =
                make_float2(acc[mi][nb][2], acc[mi][nb][3]);
        }
    }
}

extern "C" void kernel_launch(void* const* d_in, const int* in_sizes, int n_in,
                              void* d_out, int out_size) {
    const float* x      = (const float*)d_in[0];
    const float* a_ptr  = (const float*)d_in[1];
    const float* q_ptr  = (const float*)d_in[2];
    const float* coeffs = (const float*)d_in[3];
    float* y = (float*)d_out;

    cudaFuncSetAttribute(kan_mma5_kernel, cudaFuncAttributeMaxDynamicSharedMemorySize, SMEM_DYN);
    dim3 grid(OUT_DIM / BN, BATCH / BM);  // (4, 32) = 128 CTAs, single wave
    kan_mma5_kernel<<<grid, THREADS, SMEM_DYN>>>(x, a_ptr, q_ptr, coeffs, y);
}

// round 10
// speedup vs baseline: 1.2260x; 1.0414x over previous
#include <cuda_runtime.h>
#include <cuda_bf16.h>
#include <cstdint>

// y[b,o] = sum_{i,d} P_d(tanh(x[b,i])) * coeffs[i,o,d]
// GEMM M=4096 N=1024 K=8192, A generated on the fly.
// mma.sync m16n8k16 bf16, split-bf16 3-pass, fp32 accum.
// v10: pass-major ordering (P1 all-ng -> P3 all-ng -> P2 all-ng) to stretch
// accumulator RAW reuse distance from 4 HMMAs to 16 HMMAs.

#define BATCH   4096
#define IN_DIM  1024
#define OUT_DIM 1024
#define NB      8

#define BM 128
#define BN 256
#define BKI 4                  // i-values per iter
#define NIT (IN_DIM / BKI)     // 256
#define THREADS 512            // 16 warps, 4(M) x 4(N), warp tile 32x64

#define A_LD 40                // bf16 per row (80B stride, conflict-free)
#define B_LD 40
#define A_BYTES (BM * A_LD * 2)                // 10240
#define B_BYTES (BN * B_LD * 2)                // 20480
#define BUF_BYTES (2 * A_BYTES + 2 * B_BYTES)  // 61440
#define SMEM_DYN (2 * BUF_BYTES)               // 122880

__device__ __forceinline__ void ldx4(uint32_t* r, uint32_t addr) {
    asm volatile("ldmatrix.sync.aligned.m8n8.x4.shared.b16 {%0,%1,%2,%3}, [%4];"
                 : "=r"(r[0]), "=r"(r[1]), "=r"(r[2]), "=r"(r[3]) : "r"(addr));
}
__device__ __forceinline__ void mma16816(float* d, const uint32_t* a, uint32_t b0, uint32_t b1) {
    asm volatile("mma.sync.aligned.m16n8k16.row.col.f32.bf16.bf16.f32 "
                 "{%0,%1,%2,%3}, {%4,%5,%6,%7}, {%8,%9}, {%0,%1,%2,%3};"
                 : "+f"(d[0]), "+f"(d[1]), "+f"(d[2]), "+f"(d[3])
                 : "r"(a[0]), "r"(a[1]), "r"(a[2]), "r"(a[3]), "r"(b0), "r"(b1));
}
__device__ __forceinline__ uint32_t bf2u(__nv_bfloat162 v) {
    return *reinterpret_cast<uint32_t*>(&v);
}

__global__ __launch_bounds__(THREADS, 1)
void kan_mma6_kernel(const float* __restrict__ x,
                     const float* __restrict__ a_ptr,
                     const float* __restrict__ q_ptr,
                     const float* __restrict__ coeffs,
                     float* __restrict__ y) {
    extern __shared__ __align__(16) char sm[];
    const uint32_t sbase = (uint32_t)__cvta_generic_to_shared(sm);

    const float a = a_ptr[0];
    const float q = q_ptr[0];
    const int bn0 = blockIdx.x * BN;
    const int bm0 = blockIdx.y * BM;
    const int tid = threadIdx.x;
    const int lane = tid & 31;
    const int warp = tid >> 5;
    const int wm = warp >> 2;   // 0..3
    const int wn = warp & 3;    // 0..3

    float acc[2][8][4];
#pragma unroll
    for (int mi = 0; mi < 2; mi++)
#pragma unroll
        for (int nb = 0; nb < 8; nb++)
#pragma unroll
            for (int r = 0; r < 4; r++) acc[mi][nb][r] = 0.0f;

    const int aRow = wm * 32 + (lane & 15);
    const uint32_t aOff = (uint32_t)(aRow * A_LD + (lane >> 4) * 8) * 2u;
    const int bRow = wn * 64 + ((lane >> 4) << 3) + (lane & 7);
    const uint32_t bOff = (uint32_t)(bRow * B_LD + ((lane >> 3) & 1) * 8) * 2u;

    float4 pfB[4];
    float pfX;

    auto loadG = [&](int i0) {
#pragma unroll
        for (int jj = 0; jj < 4; jj++) {
            int t = tid + jj * THREADS;
            int il = t >> 9;
            int f = t & 511;
            int n = f >> 1;
            int dh = f & 1;
            pfB[jj] = *reinterpret_cast<const float4*>(
                coeffs + (size_t)(i0 + il) * (OUT_DIM * NB) + (size_t)(bn0 + n) * NB + dh * 4);
        }
        {
            int il = tid & 3;
            int row = tid >> 2;
            pfX = x[(size_t)(bm0 + row) * IN_DIM + i0 + il];
        }
    };

    auto storeS = [&](int buf) {
        char* const base = sm + buf * BUF_BYTES;
        char* const Ah = base;
        char* const Al = base + A_BYTES;
        char* const Bh = base + 2 * A_BYTES;
        char* const Bl = base + 2 * A_BYTES + B_BYTES;

#pragma unroll
        for (int jj = 0; jj < 4; jj++) {
            int t = tid + jj * THREADS;
            int il = t >> 9;
            int f = t & 511;
            int n = f >> 1;
            int dh = f & 1;
            float v[4] = {pfB[jj].x, pfB[jj].y, pfB[jj].z, pfB[jj].w};
            __nv_bfloat162 h01 = __floats2bfloat162_rn(v[0], v[1]);
            __nv_bfloat162 h23 = __floats2bfloat162_rn(v[2], v[3]);
            __nv_bfloat162 l01 = __floats2bfloat162_rn(v[0] - __bfloat162float(h01.x),
                                                       v[1] - __bfloat162float(h01.y));
            __nv_bfloat162 l23 = __floats2bfloat162_rn(v[2] - __bfloat162float(h23.x),
                                                       v[3] - __bfloat162float(h23.y));
            uint32_t off = (uint32_t)(n * B_LD + il * 8 + dh * 4) * 2u;
            *reinterpret_cast<uint2*>(Bh + off) = make_uint2(bf2u(h01), bf2u(h23));
            *reinterpret_cast<uint2*>(Bl + off) = make_uint2(bf2u(l01), bf2u(l23));
        }
        {
            int il = tid & 3;
            int row = tid >> 2;
            float xt = tanhf(pfX);
            float p[NB];
            p[0] = 1.0f;
            p[1] = xt - a;
            float qn = q;
#pragma unroll
            for (int n = 2; n < NB; n++) {
                float qn1 = qn * q;
                p[n] = (xt - (a + qn1)) * p[n - 1] - (a * qn) * p[n - 2];
                qn = qn1;
            }
            uint32_t hw[4], lw[4];
#pragma unroll
            for (int j = 0; j < 4; j++) {
                __nv_bfloat162 h = __floats2bfloat162_rn(p[2 * j], p[2 * j + 1]);
                __nv_bfloat162 l = __floats2bfloat162_rn(p[2 * j]     - __bfloat162float(h.x),
                                                         p[2 * j + 1] - __bfloat162float(h.y));
                hw[j] = bf2u(h);
                lw[j] = bf2u(l);
            }
            uint32_t off = (uint32_t)(row * A_LD + il * 8) * 2u;
            *reinterpret_cast<uint4*>(Ah + off) = make_uint4(hw[0], hw[1], hw[2], hw[3]);
            *reinterpret_cast<uint4*>(Al + off) = make_uint4(lw[0], lw[1], lw[2], lw[3]);
        }
    };

    auto compute = [&](int buf) {
        const uint32_t base = sbase + (uint32_t)buf * BUF_BYTES;
        const uint32_t pAh = base;
        const uint32_t pAl = base + A_BYTES;
        const uint32_t pBh = base + 2 * A_BYTES;
        const uint32_t pBl = base + 2 * A_BYTES + B_BYTES;
#pragma unroll
        for (int ks = 0; ks < 2; ks++) {
            const uint32_t kb = (uint32_t)ks * 32u;
            uint32_t ah[2][4], al[2][4], bh[4][4];
            ldx4(ah[0], pAh + aOff + kb);
            ldx4(ah[1], pAh + aOff + kb + (16 * A_LD * 2));
#pragma unroll
            for (int ng = 0; ng < 4; ng++)
                ldx4(bh[ng], pBh + bOff + kb + (uint32_t)ng * (16 * B_LD * 2));
            ldx4(al[0], pAl + aOff + kb);
            ldx4(al[1], pAl + aOff + kb + (16 * A_LD * 2));

            // P1: Ah * Bh over all ng (16 HMMA, all distinct accs)
#pragma unroll
            for (int ng = 0; ng < 4; ng++)
#pragma unroll
                for (int mi = 0; mi < 2; mi++) {
                    mma16816(acc[mi][2 * ng],     ah[mi], bh[ng][0], bh[ng][1]);
                    mma16816(acc[mi][2 * ng + 1], ah[mi], bh[ng][2], bh[ng][3]);
                }
            // P3: Al * Bh over all ng (acc reuse distance = 16 HMMA)
#pragma unroll
            for (int ng = 0; ng < 4; ng++)
#pragma unroll
                for (int mi = 0; mi < 2; mi++) {
                    mma16816(acc[mi][2 * ng],     al[mi], bh[ng][0], bh[ng][1]);
                    mma16816(acc[mi][2 * ng + 1], al[mi], bh[ng][2], bh[ng][3]);
                }
            // P2: Ah * Bl over all ng, 2-deep bl pipeline (al/bh dead -> regs freed)
            {
                uint32_t blc[4], bln[4];
                ldx4(blc, pBl + bOff + kb);
#pragma unroll
                for (int ng = 0; ng < 4; ng++) {
                    if (ng < 3)
                        ldx4(bln, pBl + bOff + kb + (uint32_t)(ng + 1) * (16 * B_LD * 2));
#pragma unroll
                    for (int mi = 0; mi < 2; mi++) {
                        mma16816(acc[mi][2 * ng],     ah[mi], blc[0], blc[1]);
                        mma16816(acc[mi][2 * ng + 1], ah[mi], blc[2], blc[3]);
                    }
                    if (ng < 3) {
#pragma unroll
                        for (int t = 0; t < 4; t++) blc[t] = bln[t];
                    }
                }
            }
        }
    };

    // ---- pipeline ----
    loadG(0);
    storeS(0);
    loadG(BKI);
    __syncthreads();

    for (int it = 0; it < NIT; ++it) {
        compute(it & 1);
        if (it + 1 < NIT) {
            storeS((it + 1) & 1);
            if (it + 2 < NIT) loadG((it + 2) * BKI);
            __syncthreads();
        }
    }

    // ---- epilogue ----
#pragma unroll
    for (int mi = 0; mi < 2; mi++) {
#pragma unroll
        for (int nb = 0; nb < 8; nb++) {
            int r = bm0 + wm * 32 + mi * 16 + (lane >> 2);
            int c = bn0 + wn * 64 + nb * 8 + (lane & 3) * 2;
            *reinterpret_cast<float2*>(y + (size_t)r * OUT_DIM + c) =
                make_float2(acc[mi][nb][0], acc[mi][nb][1]);
            *reinterpret_cast<float2*>(y + (size_t)(r + 8) * OUT_DIM + c) =
                make_float2(acc[mi][nb][2], acc[mi][nb][3]);
        }
    }
}

extern "C" void kernel_launch(void* const* d_in, const int* in_sizes, int n_in,
                              void* d_out, int out_size) {
    const float* x      = (const float*)d_in[0];
    const float* a_ptr  = (const float*)d_in[1];
    const float* q_ptr  = (const float*)d_in[2];
    const float* coeffs = (const float*)d_in[3];
    float* y = (float*)d_out;

    cudaFuncSetAttribute(kan_mma6_kernel, cudaFuncAttributeMaxDynamicSharedMemorySize, SMEM_DYN);
    dim3 grid(OUT_DIM / BN, BATCH / BM);  // (4, 32) = 128 CTAs, single wave
    kan_mma6_kernel<<<grid, THREADS, SMEM_DYN>>>(x, a_ptr, q_ptr, coeffs, y);
}

// round 11
// speedup vs baseline: 1.6931x; 1.3810x over previous
#include <cuda_runtime.h>
#include <cuda_fp16.h>
#include <cstdint>

// y[b,o] = sum_{i,d} P_d(tanh(x[b,i])) * coeffs[i,o,d]
// GEMM M=4096 N=1024 K=8192, A generated on the fly.
// v11: fp16 2-pass. A quantized once to fp16; B pre-scaled by 4096 and split
// into fp16 hi/lo. y = (Af*Bh + Af*Bl) / 4096. HMMA count = 2/3 of v10.

#define BATCH   4096
#define IN_DIM  1024
#define OUT_DIM 1024
#define NB      8

#define BM 128
#define BN 256
#define BKI 4                  // i-values per iter
#define NIT (IN_DIM / BKI)     // 256
#define THREADS 512            // 16 warps, 4(M) x 4(N), warp tile 32x64

#define BSCALE 4096.0f
#define INV_BSCALE (1.0f / 4096.0f)

#define A_LD 40                // fp16 per row (80B stride, conflict-free)
#define B_LD 40
#define A_BYTES (BM * A_LD * 2)                // 10240 (Af only)
#define B_BYTES (BN * B_LD * 2)                // 20480
#define BUF_BYTES (A_BYTES + 2 * B_BYTES)      // 51200: Af, Bh, Bl
#define SMEM_DYN (2 * BUF_BYTES)               // 102400

__device__ __forceinline__ void ldx4(uint32_t* r, uint32_t addr) {
    asm volatile("ldmatrix.sync.aligned.m8n8.x4.shared.b16 {%0,%1,%2,%3}, [%4];"
                 : "=r"(r[0]), "=r"(r[1]), "=r"(r[2]), "=r"(r[3]) : "r"(addr));
}
__device__ __forceinline__ void mma16816(float* d, const uint32_t* a, uint32_t b0, uint32_t b1) {
    asm volatile("mma.sync.aligned.m16n8k16.row.col.f32.f16.f16.f32 "
                 "{%0,%1,%2,%3}, {%4,%5,%6,%7}, {%8,%9}, {%0,%1,%2,%3};"
                 : "+f"(d[0]), "+f"(d[1]), "+f"(d[2]), "+f"(d[3])
                 : "r"(a[0]), "r"(a[1]), "r"(a[2]), "r"(a[3]), "r"(b0), "r"(b1));
}
__device__ __forceinline__ uint32_t h2u(__half2 v) {
    return *reinterpret_cast<uint32_t*>(&v);
}

__global__ __launch_bounds__(THREADS, 1)
void kan_fp16_kernel(const float* __restrict__ x,
                     const float* __restrict__ a_ptr,
                     const float* __restrict__ q_ptr,
                     const float* __restrict__ coeffs,
                     float* __restrict__ y) {
    extern __shared__ __align__(16) char sm[];
    const uint32_t sbase = (uint32_t)__cvta_generic_to_shared(sm);

    const float a = a_ptr[0];
    const float q = q_ptr[0];
    const int bn0 = blockIdx.x * BN;
    const int bm0 = blockIdx.y * BM;
    const int tid = threadIdx.x;
    const int lane = tid & 31;
    const int warp = tid >> 5;
    const int wm = warp >> 2;   // 0..3
    const int wn = warp & 3;    // 0..3

    float acc[2][8][4];
#pragma unroll
    for (int mi = 0; mi < 2; mi++)
#pragma unroll
        for (int nb = 0; nb < 8; nb++)
#pragma unroll
            for (int r = 0; r < 4; r++) acc[mi][nb][r] = 0.0f;

    const int aRow = wm * 32 + (lane & 15);
    const uint32_t aOff = (uint32_t)(aRow * A_LD + (lane >> 4) * 8) * 2u;
    const int bRow = wn * 64 + ((lane >> 4) << 3) + (lane & 7);
    const uint32_t bOff = (uint32_t)(bRow * B_LD + ((lane >> 3) & 1) * 8) * 2u;

    float4 pfB[4];
    float pfX;

    auto loadG = [&](int i0) {
#pragma unroll
        for (int jj = 0; jj < 4; jj++) {
            int t = tid + jj * THREADS;
            int il = t >> 9;
            int f = t & 511;
            int n = f >> 1;
            int dh = f & 1;
            pfB[jj] = *reinterpret_cast<const float4*>(
                coeffs + (size_t)(i0 + il) * (OUT_DIM * NB) + (size_t)(bn0 + n) * NB + dh * 4);
        }
        {
            int il = tid & 3;
            int row = tid >> 2;
            pfX = x[(size_t)(bm0 + row) * IN_DIM + i0 + il];
        }
    };

    auto storeS = [&](int buf) {
        char* const base = sm + buf * BUF_BYTES;
        char* const Af = base;
        char* const Bh = base + A_BYTES;
        char* const Bl = base + A_BYTES + B_BYTES;

        // B: scale by 4096, split fp16 hi/lo, [n][k] layout
#pragma unroll
        for (int jj = 0; jj < 4; jj++) {
            int t = tid + jj * THREADS;
            int il = t >> 9;
            int f = t & 511;
            int n = f >> 1;
            int dh = f & 1;
            float v[4] = {pfB[jj].x * BSCALE, pfB[jj].y * BSCALE,
                          pfB[jj].z * BSCALE, pfB[jj].w * BSCALE};
            __half2 h01 = __floats2half2_rn(v[0], v[1]);
            __half2 h23 = __floats2half2_rn(v[2], v[3]);
            __half2 l01 = __floats2half2_rn(v[0] - __low2float(h01),
                                            v[1] - __high2float(h01));
            __half2 l23 = __floats2half2_rn(v[2] - __low2float(h23),
                                            v[3] - __high2float(h23));
            uint32_t off = (uint32_t)(n * B_LD + il * 8 + dh * 4) * 2u;
            *reinterpret_cast<uint2*>(Bh + off) = make_uint2(h2u(h01), h2u(h23));
            *reinterpret_cast<uint2*>(Bl + off) = make_uint2(h2u(l01), h2u(l23));
        }
        // A: tanh + recurrence, single fp16 quantization
        {
            int il = tid & 3;
            int row = tid >> 2;
            float xt = tanhf(pfX);
            float p[NB];
            p[0] = 1.0f;
            p[1] = xt - a;
            float qn = q;
#pragma unroll
            for (int n = 2; n < NB; n++) {
                float qn1 = qn * q;
                p[n] = (xt - (a + qn1)) * p[n - 1] - (a * qn) * p[n - 2];
                qn = qn1;
            }
            uint32_t hw[4];
#pragma unroll
            for (int j = 0; j < 4; j++)
                hw[j] = h2u(__floats2half2_rn(p[2 * j], p[2 * j + 1]));
            uint32_t off = (uint32_t)(row * A_LD + il * 8) * 2u;
            *reinterpret_cast<uint4*>(Af + off) = make_uint4(hw[0], hw[1], hw[2], hw[3]);
        }
    };

    auto compute = [&](int buf) {
        const uint32_t base = sbase + (uint32_t)buf * BUF_BYTES;
        const uint32_t pAf = base;
        const uint32_t pBh = base + A_BYTES;
        const uint32_t pBl = base + A_BYTES + B_BYTES;
#pragma unroll
        for (int ks = 0; ks < 2; ks++) {
            const uint32_t kb = (uint32_t)ks * 32u;
            uint32_t af[2][4], bh[4][4];
            ldx4(af[0], pAf + aOff + kb);
            ldx4(af[1], pAf + aOff + kb + (16 * A_LD * 2));
#pragma unroll
            for (int ng = 0; ng < 4; ng++)
                ldx4(bh[ng], pBh + bOff + kb + (uint32_t)ng * (16 * B_LD * 2));

            // P1: Af * Bh over all ng (16 HMMA, distinct accs)
#pragma unroll
            for (int ng = 0; ng < 4; ng++)
#pragma unroll
                for (int mi = 0; mi < 2; mi++) {
                    mma16816(acc[mi][2 * ng],     af[mi], bh[ng][0], bh[ng][1]);
                    mma16816(acc[mi][2 * ng + 1], af[mi], bh[ng][2], bh[ng][3]);
                }
            // P2: Af * Bl over all ng, 2-deep bl pipeline (bh regs freed)
            {
                uint32_t blc[4], bln[4];
                ldx4(blc, pBl + bOff + kb);
#pragma unroll
                for (int ng = 0; ng < 4; ng++) {
                    if (ng < 3)
                        ldx4(bln, pBl + bOff + kb + (uint32_t)(ng + 1) * (16 * B_LD * 2));
#pragma unroll
                    for (int mi = 0; mi < 2; mi++) {
                        mma16816(acc[mi][2 * ng],     af[mi], blc[0], blc[1]);
                        mma16816(acc[mi][2 * ng + 1], af[mi], blc[2], blc[3]);
                    }
                    if (ng < 3) {
#pragma unroll
                        for (int t = 0; t < 4; t++) blc[t] = bln[t];
                    }
                }
            }
        }
    };

    // ---- pipeline ----
    loadG(0);
    storeS(0);
    loadG(BKI);
    __syncthreads();

    for (int it = 0; it < NIT; ++it) {
        compute(it & 1);
        if (it + 1 < NIT) {
            storeS((it + 1) & 1);
            if (it + 2 < NIT) loadG((it + 2) * BKI);
            __syncthreads();
        }
    }

    // ---- epilogue: undo B scale ----
#pragma unroll
    for (int mi = 0; mi < 2; mi++) {
#pragma unroll
        for (int nb = 0; nb < 8; nb++) {
            int r = bm0 + wm * 32 + mi * 16 + (lane >> 2);
            int c = bn0 + wn * 64 + nb * 8 + (lane & 3) * 2;
            *reinterpret_cast<float2*>(y + (size_t)r * OUT_DIM + c) =
                make_float2(acc[mi][nb][0] * INV_BSCALE, acc[mi][nb][1] * INV_BSCALE);
            *reinterpret_cast<float2*>(y + (size_t)(r + 8) * OUT_DIM + c) =
                make_float2(acc[mi][nb][2] * INV_BSCALE, acc[mi][nb][3] * INV_BSCALE);
        }
    }
}

extern "C" void kernel_launch(void* const* d_in, const int* in_sizes, int n_in,
                              void* d_out, int out_size) {
    const float* x      = (const float*)d_in[0];
    const float* a_ptr  = (const float*)d_in[1];
    const float* q_ptr  = (const float*)d_in[2];
    const float* coeffs = (const float*)d_in[3];
    float* y = (float*)d_out;

    cudaFuncSetAttribute(kan_fp16_kernel, cudaFuncAttributeMaxDynamicSharedMemorySize, SMEM_DYN);
    dim3 grid(OUT_DIM / BN, BATCH / BM);  // (4, 32) = 128 CTAs, single wave
    kan_fp16_kernel<<<grid, THREADS, SMEM_DYN>>>(x, a_ptr, q_ptr, coeffs, y);
}

// round 12
// speedup vs baseline: 1.7419x; 1.0288x over previous
#include <cuda_runtime.h>
#include <cuda_fp16.h>
#include <cstdint>

// y[b,o] = sum_{i,d} P_d(tanh(x[b,i])) * coeffs[i,o,d]
// GEMM M=4096 N=1024 K=8192, A generated on the fly.
// v12: single-pass fp16. A and B both quantized to fp16 (B pre-scaled by 4096
// to dodge subnormals; epilogue multiplies by 1/4096). Half the HMMAs of v11.

#define BATCH   4096
#define IN_DIM  1024
#define OUT_DIM 1024
#define NB      8

#define BM 128
#define BN 256
#define BKI 4                  // i-values per iter
#define NIT (IN_DIM / BKI)     // 256
#define THREADS 512            // 16 warps, 4(M) x 4(N), warp tile 32x64

#define BSCALE 4096.0f
#define INV_BSCALE (1.0f / 4096.0f)

#define A_LD 40                // fp16 per row (80B stride, conflict-free)
#define B_LD 40
#define A_BYTES (BM * A_LD * 2)            // 10240
#define B_BYTES (BN * B_LD * 2)            // 20480
#define BUF_BYTES (A_BYTES + B_BYTES)      // 30720: Af, Bf
#define SMEM_DYN (2 * BUF_BYTES)           // 61440

__device__ __forceinline__ void ldx4(uint32_t* r, uint32_t addr) {
    asm volatile("ldmatrix.sync.aligned.m8n8.x4.shared.b16 {%0,%1,%2,%3}, [%4];"
                 : "=r"(r[0]), "=r"(r[1]), "=r"(r[2]), "=r"(r[3]) : "r"(addr));
}
__device__ __forceinline__ void mma16816(float* d, const uint32_t* a, uint32_t b0, uint32_t b1) {
    asm volatile("mma.sync.aligned.m16n8k16.row.col.f32.f16.f16.f32 "
                 "{%0,%1,%2,%3}, {%4,%5,%6,%7}, {%8,%9}, {%0,%1,%2,%3};"
                 : "+f"(d[0]), "+f"(d[1]), "+f"(d[2]), "+f"(d[3])
                 : "r"(a[0]), "r"(a[1]), "r"(a[2]), "r"(a[3]), "r"(b0), "r"(b1));
}
__device__ __forceinline__ uint32_t h2u(__half2 v) {
    return *reinterpret_cast<uint32_t*>(&v);
}

__global__ __launch_bounds__(THREADS, 1)
void kan_fp16s_kernel(const float* __restrict__ x,
                      const float* __restrict__ a_ptr,
                      const float* __restrict__ q_ptr,
                      const float* __restrict__ coeffs,
                      float* __restrict__ y) {
    extern __shared__ __align__(16) char sm[];
    const uint32_t sbase = (uint32_t)__cvta_generic_to_shared(sm);

    const float a = a_ptr[0];
    const float q = q_ptr[0];
    const int bn0 = blockIdx.x * BN;
    const int bm0 = blockIdx.y * BM;
    const int tid = threadIdx.x;
    const int lane = tid & 31;
    const int warp = tid >> 5;
    const int wm = warp >> 2;   // 0..3
    const int wn = warp & 3;    // 0..3

    float acc[2][8][4];
#pragma unroll
    for (int mi = 0; mi < 2; mi++)
#pragma unroll
        for (int nb = 0; nb < 8; nb++)
#pragma unroll
            for (int r = 0; r < 4; r++) acc[mi][nb][r] = 0.0f;

    const int aRow = wm * 32 + (lane & 15);
    const uint32_t aOff = (uint32_t)(aRow * A_LD + (lane >> 4) * 8) * 2u;
    const int bRow = wn * 64 + ((lane >> 4) << 3) + (lane & 7);
    const uint32_t bOff = (uint32_t)(bRow * B_LD + ((lane >> 3) & 1) * 8) * 2u;

    float4 pfB[4];
    float pfX;

    auto loadG = [&](int i0) {
#pragma unroll
        for (int jj = 0; jj < 4; jj++) {
            int t = tid + jj * THREADS;
            int il = t >> 9;
            int f = t & 511;
            int n = f >> 1;
            int dh = f & 1;
            pfB[jj] = *reinterpret_cast<const float4*>(
                coeffs + (size_t)(i0 + il) * (OUT_DIM * NB) + (size_t)(bn0 + n) * NB + dh * 4);
        }
        {
            int il = tid & 3;
            int row = tid >> 2;
            pfX = x[(size_t)(bm0 + row) * IN_DIM + i0 + il];
        }
    };

    auto storeS = [&](int buf) {
        char* const base = sm + buf * BUF_BYTES;
        char* const Af = base;
        char* const Bf = base + A_BYTES;

        // B: scale by 4096, quantize fp16, [n][k] layout
#pragma unroll
        for (int jj = 0; jj < 4; jj++) {
            int t = tid + jj * THREADS;
            int il = t >> 9;
            int f = t & 511;
            int n = f >> 1;
            int dh = f & 1;
            __half2 h01 = __floats2half2_rn(pfB[jj].x * BSCALE, pfB[jj].y * BSCALE);
            __half2 h23 = __floats2half2_rn(pfB[jj].z * BSCALE, pfB[jj].w * BSCALE);
            uint32_t off = (uint32_t)(n * B_LD + il * 8 + dh * 4) * 2u;
            *reinterpret_cast<uint2*>(Bf + off) = make_uint2(h2u(h01), h2u(h23));
        }
        // A: tanh + recurrence, quantize fp16
        {
            int il = tid & 3;
            int row = tid >> 2;
            float xt = tanhf(pfX);
            float p[NB];
            p[0] = 1.0f;
            p[1] = xt - a;
            float qn = q;
#pragma unroll
            for (int n = 2; n < NB; n++) {
                float qn1 = qn * q;
                p[n] = (xt - (a + qn1)) * p[n - 1] - (a * qn) * p[n - 2];
                qn = qn1;
            }
            uint32_t hw[4];
#pragma unroll
            for (int j = 0; j < 4; j++)
                hw[j] = h2u(__floats2half2_rn(p[2 * j], p[2 * j + 1]));
            uint32_t off = (uint32_t)(row * A_LD + il * 8) * 2u;
            *reinterpret_cast<uint4*>(Af + off) = make_uint4(hw[0], hw[1], hw[2], hw[3]);
        }
    };

    auto compute = [&](int buf) {
        const uint32_t base = sbase + (uint32_t)buf * BUF_BYTES;
        const uint32_t pAf = base;
        const uint32_t pBf = base + A_BYTES;
#pragma unroll
        for (int ks = 0; ks < 2; ks++) {
            const uint32_t kb = (uint32_t)ks * 32u;
            uint32_t af[2][4];
            ldx4(af[0], pAf + aOff + kb);
            ldx4(af[1], pAf + aOff + kb + (16 * A_LD * 2));
            // B fragments: 2-deep pipeline over ng
            uint32_t bc[4], bn_[4];
            ldx4(bc, pBf + bOff + kb);
#pragma unroll
            for (int ng = 0; ng < 4; ng++) {
                if (ng < 3)
                    ldx4(bn_, pBf + bOff + kb + (uint32_t)(ng + 1) * (16 * B_LD * 2));
#pragma unroll
                for (int mi = 0; mi < 2; mi++) {
                    mma16816(acc[mi][2 * ng],     af[mi], bc[0], bc[1]);
                    mma16816(acc[mi][2 * ng + 1], af[mi], bc[2], bc[3]);
                }
                if (ng < 3) {
#pragma unroll
                    for (int t = 0; t < 4; t++) bc[t] = bn_[t];
                }
            }
        }
    };

    // ---- pipeline ----
    loadG(0);
    storeS(0);
    loadG(BKI);
    __syncthreads();

    for (int it = 0; it < NIT; ++it) {
        compute(it & 1);
        if (it + 1 < NIT) {
            storeS((it + 1) & 1);
            if (it + 2 < NIT) loadG((it + 2) * BKI);
            __syncthreads();
        }
    }

    // ---- epilogue: undo B scale ----
#pragma unroll
    for (int mi = 0; mi < 2; mi++) {
#pragma unroll
        for (int nb = 0; nb < 8; nb++) {
            int r = bm0 + wm * 32 + mi * 16 + (lane >> 2);
            int c = bn0 + wn * 64 + nb * 8 + (lane & 3) * 2;
            *reinterpret_cast<float2*>(y + (size_t)r * OUT_DIM + c) =
                make_float2(acc[mi][nb][0] * INV_BSCALE, acc[mi][nb][1] * INV_BSCALE);
            *reinterpret_cast<float2*>(y + (size_t)(r + 8) * OUT_DIM + c) =
                make_float2(acc[mi][nb][2] * INV_BSCALE, acc[mi][nb][3] * INV_BSCALE);
        }
    }
}

extern "C" void kernel_launch(void* const* d_in, const int* in_sizes, int n_in,
                              void* d_out, int out_size) {
    const float* x      = (const float*)d_in[0];
    const float* a_ptr  = (const float*)d_in[1];
    const float* q_ptr  = (const float*)d_in[2];
    const float* coeffs = (const float*)d_in[3];
    float* y = (float*)d_out;

    cudaFuncSetAttribute(kan_fp16s_kernel, cudaFuncAttributeMaxDynamicSharedMemorySize, SMEM_DYN);
    dim3 grid(OUT_DIM / BN, BATCH / BM);  // (4, 32) = 128 CTAs, single wave
    kan_fp16s_kernel<<<grid, THREADS, SMEM_DYN>>>(x, a_ptr, q_ptr, coeffs, y);
}

// round 13
// speedup vs baseline: 2.3131x; 1.3279x over previous
#include <cuda_runtime.h>
#include <cuda_fp16.h>
#include <cstdint>

// y[b,o] = sum_{i,d} P_d(tanh(x[b,i])) * coeffs[i,o,d]
// GEMM M=4096 N=1024 K=8192. v13: single-pass fp16, 64x64 warp tiles (8 warps)
// to cut LDS/HMMA from 192B to 128B. B pre-converted to fp16 (x4096) by a prep
// kernel into a __device__ global; main loop pulls B via cp.async (no RF
// staging). A (tanh+recurrence) stays fused, 2 values/thread.

#define BATCH   4096
#define IN_DIM  1024
#define OUT_DIM 1024
#define NB      8
#define KTOT    (IN_DIM * NB)   // 8192

#define BM 128
#define BN 256
#define BKI 4                  // i per iter -> 32 k
#define NIT (IN_DIM / BKI)     // 256
#define THREADS 256            // 8 warps, 2(M) x 4(N), warp tile 64x64

#define BSCALE 4096.0f
#define INV_BSCALE (1.0f / 4096.0f)

#define A_LD 40                // fp16 per row (80B stride, conflict-free)
#define B_LD 40
#define A_BYTES (BM * A_LD * 2)            // 10240
#define B_BYTES (BN * B_LD * 2)            // 20480
#define BUF_BYTES (A_BYTES + B_BYTES)      // 30720
#define SMEM_DYN (2 * BUF_BYTES)           // 61440

// B in fp16, scaled by 4096, layout [o][k], k = i*8 + d
__device__ __align__(16) __half gBf[(size_t)OUT_DIM * KTOT];

__device__ __forceinline__ void ldx4(uint32_t* r, uint32_t addr) {
    asm volatile("ldmatrix.sync.aligned.m8n8.x4.shared.b16 {%0,%1,%2,%3}, [%4];"
                 : "=r"(r[0]), "=r"(r[1]), "=r"(r[2]), "=r"(r[3]) : "r"(addr));
}
__device__ __forceinline__ void mma16816(float* d, const uint32_t* a, uint32_t b0, uint32_t b1) {
    asm volatile("mma.sync.aligned.m16n8k16.row.col.f32.f16.f16.f32 "
                 "{%0,%1,%2,%3}, {%4,%5,%6,%7}, {%8,%9}, {%0,%1,%2,%3};"
                 : "+f"(d[0]), "+f"(d[1]), "+f"(d[2]), "+f"(d[3])
                 : "r"(a[0]), "r"(a[1]), "r"(a[2]), "r"(a[3]), "r"(b0), "r"(b1));
}
__device__ __forceinline__ void cpa16(uint32_t dst, const void* src) {
    asm volatile("cp.async.cg.shared.global [%0], [%1], 16;" :: "r"(dst), "l"(src));
}
__device__ __forceinline__ uint32_t h2u(__half2 v) {
    return *reinterpret_cast<uint32_t*>(&v);
}

// ---- prep: coeffs fp32 [i][o][d] -> gBf fp16 [o][i*8+d], scaled ----
__global__ __launch_bounds__(256)
void prep_b_kernel(const float* __restrict__ coeffs) {
    int g = blockIdx.x * 256 + threadIdx.x;   // 0 .. 1048575
    int o = g >> 10;
    int i = g & 1023;
    const float* src = coeffs + ((size_t)i * OUT_DIM + o) * NB;
    float4 v0 = *reinterpret_cast<const float4*>(src);
    float4 v1 = *reinterpret_cast<const float4*>(src + 4);
    __half2 h0 = __floats2half2_rn(v0.x * BSCALE, v0.y * BSCALE);
    __half2 h1 = __floats2half2_rn(v0.z * BSCALE, v0.w * BSCALE);
    __half2 h2 = __floats2half2_rn(v1.x * BSCALE, v1.y * BSCALE);
    __half2 h3 = __floats2half2_rn(v1.z * BSCALE, v1.w * BSCALE);
    *reinterpret_cast<uint4*>(&gBf[(size_t)o * KTOT + (size_t)i * NB]) =
        make_uint4(h2u(h0), h2u(h1), h2u(h2), h2u(h3));
}

__global__ __launch_bounds__(THREADS, 1)
void kan_v13_kernel(const float* __restrict__ x,
                    const float* __restrict__ a_ptr,
                    const float* __restrict__ q_ptr,
                    float* __restrict__ y) {
    extern __shared__ __align__(16) char sm[];
    const uint32_t sbase = (uint32_t)__cvta_generic_to_shared(sm);

    const float a = a_ptr[0];
    const float q = q_ptr[0];
    const int bn0 = blockIdx.x * BN;
    const int bm0 = blockIdx.y * BM;
    const int tid = threadIdx.x;
    const int lane = tid & 31;
    const int warp = tid >> 5;
    const int wm = warp >> 2;   // 0..1  (64-row groups)
    const int wn = warp & 3;    // 0..3  (64-col groups)

    float acc[4][8][4];
#pragma unroll
    for (int mi = 0; mi < 4; mi++)
#pragma unroll
        for (int nb = 0; nb < 8; nb++)
#pragma unroll
            for (int r = 0; r < 4; r++) acc[mi][nb][r] = 0.0f;

    const int aRow = wm * 64 + (lane & 15);
    const uint32_t aOff = (uint32_t)(aRow * A_LD + (lane >> 4) * 8) * 2u;
    const int bRow = wn * 64 + ((lane >> 4) << 3) + (lane & 7);
    const uint32_t bOff = (uint32_t)(bRow * B_LD + ((lane >> 3) & 1) * 8) * 2u;

    float pfX[2];

    auto loadGA = [&](int i0) {
#pragma unroll
        for (int jj = 0; jj < 2; jj++) {
            int e = tid + jj * THREADS;     // 0..511
            int il = e & 3;
            int row = e >> 2;
            pfX[jj] = x[(size_t)(bm0 + row) * IN_DIM + i0 + il];
        }
    };

    auto storeA = [&](int buf) {
        char* const Af = sm + buf * BUF_BYTES;
#pragma unroll
        for (int jj = 0; jj < 2; jj++) {
            int e = tid + jj * THREADS;
            int il = e & 3;
            int row = e >> 2;
            float xt = tanhf(pfX[jj]);
            float p[NB];
            p[0] = 1.0f;
            p[1] = xt - a;
            float qn = q;
#pragma unroll
            for (int n = 2; n < NB; n++) {
                float qn1 = qn * q;
                p[n] = (xt - (a + qn1)) * p[n - 1] - (a * qn) * p[n - 2];
                qn = qn1;
            }
            uint32_t hw[4];
#pragma unroll
            for (int j = 0; j < 4; j++)
                hw[j] = h2u(__floats2half2_rn(p[2 * j], p[2 * j + 1]));
            *reinterpret_cast<uint4*>(Af + (uint32_t)(row * A_LD + il * 8) * 2u) =
                make_uint4(hw[0], hw[1], hw[2], hw[3]);
        }
    };

    auto cpB = [&](int buf, int it) {
        const uint32_t dstB = sbase + (uint32_t)buf * BUF_BYTES + A_BYTES;
        const int k0 = it * (BKI * NB);   // 32 per iter
#pragma unroll
        for (int jj = 0; jj < 4; jj++) {
            int c = tid + jj * THREADS;   // 0..1023
            int row = c >> 2;             // 0..255
            int ch = c & 3;
            const __half* src = gBf + (size_t)(bn0 + row) * KTOT + k0 + ch * 8;
            cpa16(dstB + (uint32_t)(row * B_LD + ch * 8) * 2u, src);
        }
        asm volatile("cp.async.commit_group;" ::: "memory");
    };

    auto compute = [&](int buf) {
        const uint32_t base = sbase + (uint32_t)buf * BUF_BYTES;
        const uint32_t pAf = base;
        const uint32_t pBf = base + A_BYTES;
#pragma unroll
        for (int ks = 0; ks < 2; ks++) {
            const uint32_t kb = (uint32_t)ks * 32u;
            uint32_t af[4][4];
#pragma unroll
            for (int mi = 0; mi < 4; mi++)
                ldx4(af[mi], pAf + aOff + kb + (uint32_t)mi * (16 * A_LD * 2));
            // B: 2-deep pipeline over ng
            uint32_t bc[4], bn_[4];
            ldx4(bc, pBf + bOff + kb);
#pragma unroll
            for (int ng = 0; ng < 4; ng++) {
                if (ng < 3)
                    ldx4(bn_, pBf + bOff + kb + (uint32_t)(ng + 1) * (16 * B_LD * 2));
#pragma unroll
                for (int mi = 0; mi < 4; mi++) {
                    mma16816(acc[mi][2 * ng],     af[mi], bc[0], bc[1]);
                    mma16816(acc[mi][2 * ng + 1], af[mi], bc[2], bc[3]);
                }
                if (ng < 3) {
#pragma unroll
                    for (int t = 0; t < 4; t++) bc[t] = bn_[t];
                }
            }
        }
    };

    // ---- prologue ----
    loadGA(0);
    storeA(0);
    loadGA(BKI);
    storeA(1);
    cpB(0, 0);
    cpB(1, 1);
    loadGA(2 * BKI);           // pfX holds x(it=2)
    asm volatile("cp.async.wait_group 0;" ::: "memory");
    __syncthreads();

    // ---- main loop: 1 barrier/iter ----
    for (int it = 0; it < NIT; ++it) {
        compute(it & 1);
        if (it + 1 < NIT) {
            asm volatile("cp.async.wait_group 0;" ::: "memory");  // B(it+1) complete
            __syncthreads();                                       // readers done + visibility
            if (it + 2 < NIT) {
                storeA(it & 1);          // A for it+2 (pfX)
                cpB(it & 1, it + 2);     // B for it+2
            }
            if (it + 3 < NIT) loadGA((it + 3) * BKI);
        }
    }

    // ---- epilogue: undo B scale ----
#pragma unroll
    for (int mi = 0; mi < 4; mi++) {
#pragma unroll
        for (int nb = 0; nb < 8; nb++) {
            int r = bm0 + wm * 64 + mi * 16 + (lane >> 2);
            int c = bn0 + wn * 64 + nb * 8 + (lane & 3) * 2;
            *reinterpret_cast<float2*>(y + (size_t)r * OUT_DIM + c) =
                make_float2(acc[mi][nb][0] * INV_BSCALE, acc[mi][nb][1] * INV_BSCALE);
            *reinterpret_cast<float2*>(y + (size_t)(r + 8) * OUT_DIM + c) =
                make_float2(acc[mi][nb][2] * INV_BSCALE, acc[mi][nb][3] * INV_BSCALE);
        }
    }
}

extern "C" void kernel_launch(void* const* d_in, const int* in_sizes, int n_in,
                              void* d_out, int out_size) {
    const float* x      = (const float*)d_in[0];
    const float* a_ptr  = (const float*)d_in[1];
    const float* q_ptr  = (const float*)d_in[2];
    const float* coeffs = (const float*)d_in[3];
    float* y = (float*)d_out;

    prep_b_kernel<<<(OUT_DIM * IN_DIM) / 256, 256>>>(coeffs);

    cudaFuncSetAttribute(kan_v13_kernel, cudaFuncAttributeMaxDynamicSharedMemorySize, SMEM_DYN);
    dim3 grid(OUT_DIM / BN, BATCH / BM);  // (4, 32) = 128 CTAs, single wave
    kan_v13_kernel<<<grid, THREADS, SMEM_DYN>>>(x, a_ptr, q_ptr, y);
}

// round 15
// speedup vs baseline: 2.6200x; 1.1327x over previous
#include <cuda_runtime.h>
#include <cuda_fp16.h>
#include <cstdint>

// y[b,o] = sum_{i,d} P_d(tanh(x[b,i])) * coeffs[i,o,d]
// GEMM M=4096 N=1024 K=8192. v14: v13 + 4-stage cp.async ring (wait_group 2)
// so B-tile L2 latency has ~3 compute phases of slack instead of ~1.
// Single-pass fp16, 64x64 warp tiles, 8 warps, B pre-converted by prep kernel.

#define BATCH   4096
#define IN_DIM  1024
#define OUT_DIM 1024
#define NB      8
#define KTOT    (IN_DIM * NB)   // 8192

#define BM 128
#define BN 256
#define BKI 4                  // i per iter -> 32 k
#define NIT (IN_DIM / BKI)     // 256
#define THREADS 256            // 8 warps, 2(M) x 4(N), warp tile 64x64

#define BSCALE 4096.0f
#define INV_BSCALE (1.0f / 4096.0f)

#define A_LD 40                // fp16 per row (80B stride, conflict-free)
#define B_LD 40
#define A_BYTES (BM * A_LD * 2)            // 10240
#define B_BYTES (BN * B_LD * 2)            // 20480
#define BUF_BYTES (A_BYTES + B_BYTES)      // 30720
#define STAGES 4
#define SMEM_DYN (STAGES * BUF_BYTES)      // 122880

// B in fp16, scaled by 4096, layout [o][k], k = i*8 + d
__device__ __align__(16) __half gBf[(size_t)OUT_DIM * KTOT];

__device__ __forceinline__ void ldx4(uint32_t* r, uint32_t addr) {
    asm volatile("ldmatrix.sync.aligned.m8n8.x4.shared.b16 {%0,%1,%2,%3}, [%4];"
                 : "=r"(r[0]), "=r"(r[1]), "=r"(r[2]), "=r"(r[3]) : "r"(addr));
}
__device__ __forceinline__ void mma16816(float* d, const uint32_t* a, uint32_t b0, uint32_t b1) {
    asm volatile("mma.sync.aligned.m16n8k16.row.col.f32.f16.f16.f32 "
                 "{%0,%1,%2,%3}, {%4,%5,%6,%7}, {%8,%9}, {%0,%1,%2,%3};"
                 : "+f"(d[0]), "+f"(d[1]), "+f"(d[2]), "+f"(d[3])
                 : "r"(a[0]), "r"(a[1]), "r"(a[2]), "r"(a[3]), "r"(b0), "r"(b1));
}
__device__ __forceinline__ void cpa16(uint32_t dst, const void* src) {
    asm volatile("cp.async.cg.shared.global [%0], [%1], 16;" :: "r"(dst), "l"(src));
}
__device__ __forceinline__ uint32_t h2u(__half2 v) {
    return *reinterpret_cast<uint32_t*>(&v);
}

// ---- prep: coeffs fp32 [i][o][d] -> gBf fp16 [o][i*8+d], scaled ----
__global__ __launch_bounds__(256)
void prep_b_kernel(const float* __restrict__ coeffs) {
    int g = blockIdx.x * 256 + threadIdx.x;   // 0 .. 1048575
    int o = g >> 10;
    int i = g & 1023;
    const float* src = coeffs + ((size_t)i * OUT_DIM + o) * NB;
    float4 v0 = *reinterpret_cast<const float4*>(src);
    float4 v1 = *reinterpret_cast<const float4*>(src + 4);
    __half2 h0 = __floats2half2_rn(v0.x * BSCALE, v0.y * BSCALE);
    __half2 h1 = __floats2half2_rn(v0.z * BSCALE, v0.w * BSCALE);
    __half2 h2 = __floats2half2_rn(v1.x * BSCALE, v1.y * BSCALE);
    __half2 h3 = __floats2half2_rn(v1.z * BSCALE, v1.w * BSCALE);
    *reinterpret_cast<uint4*>(&gBf[(size_t)o * KTOT + (size_t)i * NB]) =
        make_uint4(h2u(h0), h2u(h1), h2u(h2), h2u(h3));
}

__global__ __launch_bounds__(THREADS, 1)
void kan_v14_kernel(const float* __restrict__ x,
                    const float* __restrict__ a_ptr,
                    const float* __restrict__ q_ptr,
                    float* __restrict__ y) {
    extern __shared__ __align__(16) char sm[];
    const uint32_t sbase = (uint32_t)__cvta_generic_to_shared(sm);

    const float a = a_ptr[0];
    const float q = q_ptr[0];
    const int bn0 = blockIdx.x * BN;
    const int bm0 = blockIdx.y * BM;
    const int tid = threadIdx.x;
    const int lane = tid & 31;
    const int warp = tid >> 5;
    const int wm = warp >> 2;   // 0..1
    const int wn = warp & 3;    // 0..3

    float acc[4][8][4];
#pragma unroll
    for (int mi = 0; mi < 4; mi++)
#pragma unroll
        for (int nb = 0; nb < 8; nb++)
#pragma unroll
            for (int r = 0; r < 4; r++) acc[mi][nb][r] = 0.0f;

    const int aRow = wm * 64 + (lane & 15);
    const uint32_t aOff = (uint32_t)(aRow * A_LD + (lane >> 4) * 8) * 2u;
    const int bRow = wn * 64 + ((lane >> 4) << 3) + (lane & 7);
    const uint32_t bOff = (uint32_t)(bRow * B_LD + ((lane >> 3) & 1) * 8) * 2u;

    float pfX[2];

    auto loadGA = [&](int i0) {
#pragma unroll
        for (int jj = 0; jj < 2; jj++) {
            int e = tid + jj * THREADS;     // 0..511
            int il = e & 3;
            int row = e >> 2;
            pfX[jj] = x[(size_t)(bm0 + row) * IN_DIM + i0 + il];
        }
    };

    auto storeA = [&](int buf) {
        char* const Af = sm + buf * BUF_BYTES;
#pragma unroll
        for (int jj = 0; jj < 2; jj++) {
            int e = tid + jj * THREADS;
            int il = e & 3;
            int row = e >> 2;
            float xt = tanhf(pfX[jj]);
            float p[NB];
            p[0] = 1.0f;
            p[1] = xt - a;
            float qn = q;
#pragma unroll
            for (int n = 2; n < NB; n++) {
                float qn1 = qn * q;
                p[n] = (xt - (a + qn1)) * p[n - 1] - (a * qn) * p[n - 2];
                qn = qn1;
            }
            uint32_t hw[4];
#pragma unroll
            for (int j = 0; j < 4; j++)
                hw[j] = h2u(__floats2half2_rn(p[2 * j], p[2 * j + 1]));
            *reinterpret_cast<uint4*>(Af + (uint32_t)(row * A_LD + il * 8) * 2u) =
                make_uint4(hw[0], hw[1], hw[2], hw[3]);
        }
    };

    auto cpB = [&](int buf, int it) {
        const uint32_t dstB = sbase + (uint32_t)buf * BUF_BYTES + A_BYTES;
        const int k0 = it * (BKI * NB);
#pragma unroll
        for (int jj = 0; jj < 4; jj++) {
            int c = tid + jj * THREADS;   // 0..1023
            int row = c >> 2;             // 0..255
            int ch = c & 3;
            const __half* src = gBf + (size_t)(bn0 + row) * KTOT + k0 + ch * 8;
            cpa16(dstB + (uint32_t)(row * B_LD + ch * 8) * 2u, src);
        }
        asm volatile("cp.async.commit_group;" ::: "memory");
    };

    auto compute = [&](int buf) {
        const uint32_t base = sbase + (uint32_t)buf * BUF_BYTES;
        const uint32_t pAf = base;
        const uint32_t pBf = base + A_BYTES;
#pragma unroll
        for (int ks = 0; ks < 2; ks++) {
            const uint32_t kb = (uint32_t)ks * 32u;
            uint32_t af[4][4];
#pragma unroll
            for (int mi = 0; mi < 4; mi++)
                ldx4(af[mi], pAf + aOff + kb + (uint32_t)mi * (16 * A_LD * 2));
            uint32_t bc[4], bn_[4];
            ldx4(bc, pBf + bOff + kb);
#pragma unroll
            for (int ng = 0; ng < 4; ng++) {
                if (ng < 3)
                    ldx4(bn_, pBf + bOff + kb + (uint32_t)(ng + 1) * (16 * B_LD * 2));
#pragma unroll
                for (int mi = 0; mi < 4; mi++) {
                    mma16816(acc[mi][2 * ng],     af[mi], bc[0], bc[1]);
                    mma16816(acc[mi][2 * ng + 1], af[mi], bc[2], bc[3]);
                }
                if (ng < 3) {
#pragma unroll
                    for (int t = 0; t < 4; t++) bc[t] = bn_[t];
                }
            }
        }
    };

    // ---- prologue: fill stages 0..2, pfX holds x(3) ----
    loadGA(0);          storeA(0); cpB(0, 0);
    loadGA(1 * BKI);    storeA(1); cpB(1, 1);
    loadGA(2 * BKI);    storeA(2); cpB(2, 2);
    loadGA(3 * BKI);
    asm volatile("cp.async.wait_group 2;" ::: "memory");   // group(0) done
    __syncthreads();

    // ---- main loop: 1 barrier/iter, ~3 computes of cp.async slack ----
    for (int it = 0; it < NIT; ++it) {
        compute(it & 3);
        if (it + 1 < NIT) {
            if (it + 3 < NIT) {
                storeA((it + 3) & 3);          // A for it+3 (pfX)
                cpB((it + 3) & 3, it + 3);     // B for it+3
            }
            if (it + 4 < NIT) loadGA((it + 4) * BKI);
            // drain so that group(it+1) is complete
            if (it + 3 < NIT) {
                asm volatile("cp.async.wait_group 2;" ::: "memory");
            } else if (it + 2 < NIT) {
                asm volatile("cp.async.wait_group 1;" ::: "memory");
            } else {
                asm volatile("cp.async.wait_group 0;" ::: "memory");
            }
            __syncthreads();
        }
    }

    // ---- epilogue: undo B scale ----
#pragma unroll
    for (int mi = 0; mi < 4; mi++) {
#pragma unroll
        for (int nb = 0; nb < 8; nb++) {
            int r = bm0 + wm * 64 + mi * 16 + (lane >> 2);
            int c = bn0 + wn * 64 + nb * 8 + (lane & 3) * 2;
            *reinterpret_cast<float2*>(y + (size_t)r * OUT_DIM + c) =
                make_float2(acc[mi][nb][0] * INV_BSCALE, acc[mi][nb][1] * INV_BSCALE);
            *reinterpret_cast<float2*>(y + (size_t)(r + 8) * OUT_DIM + c) =
                make_float2(acc[mi][nb][2] * INV_BSCALE, acc[mi][nb][3] * INV_BSCALE);
        }
    }
}

extern "C" void kernel_launch(void* const* d_in, const int* in_sizes, int n_in,
                              void* d_out, int out_size) {
    const float* x      = (const float*)d_in[0];
    const float* a_ptr  = (const float*)d_in[1];
    const float* q_ptr  = (const float*)d_in[2];
    const float* coeffs = (const float*)d_in[3];
    float* y = (float*)d_out;

    prep_b_kernel<<<(OUT_DIM * IN_DIM) / 256, 256>>>(coeffs);

    cudaFuncSetAttribute(kan_v14_kernel, cudaFuncAttributeMaxDynamicSharedMemorySize, SMEM_DYN);
    dim3 grid(OUT_DIM / BN, BATCH / BM);  // (4, 32) = 128 CTAs, single wave
    kan_v14_kernel<<<grid, THREADS, SMEM_DYN>>>(x, a_ptr, q_ptr, y);
}

// round 16
// speedup vs baseline: 2.8961x; 1.1054x over previous
#include <cuda_runtime.h>
#include <cuda_fp16.h>
#include <cstdint>

// y[b,o] = sum_{i,d} P_d(tanh(x[b,i])) * coeffs[i,o,d]
// GEMM M=4096 N=1024 K=8192. v16: v14 with double K-tile (KK=64, NIT=128) to
// halve per-iteration fixed costs (barrier, waits, ks-head exposure), 3-stage
// cp.async ring. Single-pass fp16, 64x64 warp tiles, 8 warps.

#define BATCH   4096
#define IN_DIM  1024
#define OUT_DIM 1024
#define NB      8
#define KTOT    (IN_DIM * NB)   // 8192

#define BM 128
#define BN 256
#define BKI 8                  // i per iter -> 64 k
#define KK  (BKI * NB)         // 64
#define NIT (IN_DIM / BKI)     // 128
#define THREADS 256            // 8 warps, 2(M) x 4(N), warp tile 64x64

#define BSCALE 4096.0f
#define INV_BSCALE (1.0f / 4096.0f)

#define A_LD 72                // fp16 per row (144B stride, conflict-free)
#define B_LD 72
#define A_BYTES (BM * A_LD * 2)            // 18432
#define B_BYTES (BN * B_LD * 2)            // 36864
#define BUF_BYTES (A_BYTES + B_BYTES)      // 55296
#define STAGES 3
#define SMEM_DYN (STAGES * BUF_BYTES)      // 165888

// B in fp16, scaled by 4096, layout [o][k], k = i*8 + d
__device__ __align__(16) __half gBf[(size_t)OUT_DIM * KTOT];

__device__ __forceinline__ void ldx4(uint32_t* r, uint32_t addr) {
    asm volatile("ldmatrix.sync.aligned.m8n8.x4.shared.b16 {%0,%1,%2,%3}, [%4];"
                 : "=r"(r[0]), "=r"(r[1]), "=r"(r[2]), "=r"(r[3]) : "r"(addr));
}
__device__ __forceinline__ void mma16816(float* d, const uint32_t* a, uint32_t b0, uint32_t b1) {
    asm volatile("mma.sync.aligned.m16n8k16.row.col.f32.f16.f16.f32 "
                 "{%0,%1,%2,%3}, {%4,%5,%6,%7}, {%8,%9}, {%0,%1,%2,%3};"
                 : "+f"(d[0]), "+f"(d[1]), "+f"(d[2]), "+f"(d[3])
                 : "r"(a[0]), "r"(a[1]), "r"(a[2]), "r"(a[3]), "r"(b0), "r"(b1));
}
__device__ __forceinline__ void cpa16(uint32_t dst, const void* src) {
    asm volatile("cp.async.cg.shared.global [%0], [%1], 16;" :: "r"(dst), "l"(src));
}
__device__ __forceinline__ uint32_t h2u(__half2 v) {
    return *reinterpret_cast<uint32_t*>(&v);
}

// ---- prep: coeffs fp32 [i][o][d] -> gBf fp16 [o][i*8+d], scaled ----
__global__ __launch_bounds__(256)
void prep_b_kernel(const float* __restrict__ coeffs) {
    int g = blockIdx.x * 256 + threadIdx.x;   // 0 .. 1048575
    int o = g >> 10;
    int i = g & 1023;
    const float* src = coeffs + ((size_t)i * OUT_DIM + o) * NB;
    float4 v0 = *reinterpret_cast<const float4*>(src);
    float4 v1 = *reinterpret_cast<const float4*>(src + 4);
    __half2 h0 = __floats2half2_rn(v0.x * BSCALE, v0.y * BSCALE);
    __half2 h1 = __floats2half2_rn(v0.z * BSCALE, v0.w * BSCALE);
    __half2 h2 = __floats2half2_rn(v1.x * BSCALE, v1.y * BSCALE);
    __half2 h3 = __floats2half2_rn(v1.z * BSCALE, v1.w * BSCALE);
    *reinterpret_cast<uint4*>(&gBf[(size_t)o * KTOT + (size_t)i * NB]) =
        make_uint4(h2u(h0), h2u(h1), h2u(h2), h2u(h3));
}

__global__ __launch_bounds__(THREADS, 1)
void kan_v16_kernel(const float* __restrict__ x,
                    const float* __restrict__ a_ptr,
                    const float* __restrict__ q_ptr,
                    float* __restrict__ y) {
    extern __shared__ __align__(16) char sm[];
    const uint32_t sbase = (uint32_t)__cvta_generic_to_shared(sm);

    const float a = a_ptr[0];
    const float q = q_ptr[0];
    const int bn0 = blockIdx.x * BN;
    const int bm0 = blockIdx.y * BM;
    const int tid = threadIdx.x;
    const int lane = tid & 31;
    const int warp = tid >> 5;
    const int wm = warp >> 2;   // 0..1
    const int wn = warp & 3;    // 0..3

    float acc[4][8][4];
#pragma unroll
    for (int mi = 0; mi < 4; mi++)
#pragma unroll
        for (int nb = 0; nb < 8; nb++)
#pragma unroll
            for (int r = 0; r < 4; r++) acc[mi][nb][r] = 0.0f;

    const int aRow = wm * 64 + (lane & 15);
    const uint32_t aOff = (uint32_t)(aRow * A_LD + (lane >> 4) * 8) * 2u;
    const int bRow = wn * 64 + ((lane >> 4) << 3) + (lane & 7);
    const uint32_t bOff = (uint32_t)(bRow * B_LD + ((lane >> 3) & 1) * 8) * 2u;

    float pfX[4];

    auto loadGA = [&](int i0) {
#pragma unroll
        for (int jj = 0; jj < 4; jj++) {
            int e = tid + jj * THREADS;     // 0..1023
            int il = e & 7;
            int row = e >> 3;
            pfX[jj] = x[(size_t)(bm0 + row) * IN_DIM + i0 + il];
        }
    };

    auto storeA = [&](int buf) {
        char* const Af = sm + buf * BUF_BYTES;
#pragma unroll
        for (int jj = 0; jj < 4; jj++) {
            int e = tid + jj * THREADS;
            int il = e & 7;
            int row = e >> 3;
            float xt = tanhf(pfX[jj]);
            float p[NB];
            p[0] = 1.0f;
            p[1] = xt - a;
            float qn = q;
#pragma unroll
            for (int n = 2; n < NB; n++) {
                float qn1 = qn * q;
                p[n] = (xt - (a + qn1)) * p[n - 1] - (a * qn) * p[n - 2];
                qn = qn1;
            }
            uint32_t hw[4];
#pragma unroll
            for (int j = 0; j < 4; j++)
                hw[j] = h2u(__floats2half2_rn(p[2 * j], p[2 * j + 1]));
            *reinterpret_cast<uint4*>(Af + (uint32_t)(row * A_LD + il * 8) * 2u) =
                make_uint4(hw[0], hw[1], hw[2], hw[3]);
        }
    };

    auto cpB = [&](int buf, int it) {
        const uint32_t dstB = sbase + (uint32_t)buf * BUF_BYTES + A_BYTES;
        const int k0 = it * KK;   // 64 k per iter
#pragma unroll
        for (int jj = 0; jj < 8; jj++) {
            int c = tid + jj * THREADS;   // 0..2047
            int row = c >> 3;             // 0..255
            int ch = c & 7;               // 16B chunk within 128B row
            const __half* src = gBf + (size_t)(bn0 + row) * KTOT + k0 + ch * 8;
            cpa16(dstB + (uint32_t)(row * B_LD + ch * 8) * 2u, src);
        }
        asm volatile("cp.async.commit_group;" ::: "memory");
    };

    auto compute = [&](int buf) {
        const uint32_t base = sbase + (uint32_t)buf * BUF_BYTES;
        const uint32_t pAf = base;
        const uint32_t pBf = base + A_BYTES;
#pragma unroll
        for (int ks = 0; ks < 4; ks++) {       // 4 halves of 16 k
            const uint32_t kb = (uint32_t)ks * 32u;
            uint32_t af[4][4];
#pragma unroll
            for (int mi = 0; mi < 4; mi++)
                ldx4(af[mi], pAf + aOff + kb + (uint32_t)mi * (16 * A_LD * 2));
            uint32_t bc[4], bn_[4];
            ldx4(bc, pBf + bOff + kb);
#pragma unroll
            for (int ng = 0; ng < 4; ng++) {
                if (ng < 3)
                    ldx4(bn_, pBf + bOff + kb + (uint32_t)(ng + 1) * (16 * B_LD * 2));
#pragma unroll
                for (int mi = 0; mi < 4; mi++) {
                    mma16816(acc[mi][2 * ng],     af[mi], bc[0], bc[1]);
                    mma16816(acc[mi][2 * ng + 1], af[mi], bc[2], bc[3]);
                }
                if (ng < 3) {
#pragma unroll
                    for (int t = 0; t < 4; t++) bc[t] = bn_[t];
                }
            }
        }
    };

    // ---- prologue: fill stages 0..1, pfX holds x(2) ----
    loadGA(0);         storeA(0); cpB(0, 0);
    loadGA(1 * BKI);   storeA(1); cpB(1, 1);
    loadGA(2 * BKI);
    asm volatile("cp.async.wait_group 1;" ::: "memory");   // group(0) done
    __syncthreads();

    // ---- main loop ----
    for (int it = 0; it < NIT; ++it) {
        compute(it % 3);
        if (it + 1 < NIT) {
            if (it + 2 < NIT) {
                storeA((it + 2) % 3);
                cpB((it + 2) % 3, it + 2);
            }
            if (it + 3 < NIT) loadGA((it + 3) * BKI);
            if (it + 2 < NIT) {
                asm volatile("cp.async.wait_group 1;" ::: "memory");
            } else {
                asm volatile("cp.async.wait_group 0;" ::: "memory");
            }
            __syncthreads();
        }
    }

    // ---- epilogue: undo B scale ----
#pragma unroll
    for (int mi = 0; mi < 4; mi++) {
#pragma unroll
        for (int nb = 0; nb < 8; nb++) {
            int r = bm0 + wm * 64 + mi * 16 + (lane >> 2);
            int c = bn0 + wn * 64 + nb * 8 + (lane & 3) * 2;
            *reinterpret_cast<float2*>(y + (size_t)r * OUT_DIM + c) =
                make_float2(acc[mi][nb][0] * INV_BSCALE, acc[mi][nb][1] * INV_BSCALE);
            *reinterpret_cast<float2*>(y + (size_t)(r + 8) * OUT_DIM + c) =
                make_float2(acc[mi][nb][2] * INV_BSCALE, acc[mi][nb][3] * INV_BSCALE);
        }
    }
}

extern "C" void kernel_launch(void* const* d_in, const int* in_sizes, int n_in,
                              void* d_out, int out_size) {
    const float* x      = (const float*)d_in[0];
    const float* a_ptr  = (const float*)d_in[1];
    const float* q_ptr  = (const float*)d_in[2];
    const float* coeffs = (const float*)d_in[3];
    float* y = (float*)d_out;

    prep_b_kernel<<<(OUT_DIM * IN_DIM) / 256, 256>>>(coeffs);

    cudaFuncSetAttribute(kan_v16_kernel, cudaFuncAttributeMaxDynamicSharedMemorySize, SMEM_DYN);
    dim3 grid(OUT_DIM / BN, BATCH / BM);  // (4, 32) = 128 CTAs, single wave
    kan_v16_kernel<<<grid, THREADS, SMEM_DYN>>>(x, a_ptr, q_ptr, y);
}

// round 17
// speedup vs baseline: 3.0221x; 1.0435x over previous
#include <cuda_runtime.h>
#include <cuda_fp16.h>
#include <cstdint>

// y[b,o] = sum_{i,d} P_d(tanh(x[b,i])) * coeffs[i,o,d]
// GEMM M=4096 N=1024 K=8192. v17: BOTH operands precomputed to fp16 globals by
// prep kernels (A: tanh+recurrence, bit-identical to the old in-loop code).
// Hot loop is pure cp.async + ldmatrix + HMMA. KK=64, 3-stage ring, 64x64 warp
// tiles, 8 warps, single-pass fp16 (B pre-scaled by 4096).

#define BATCH   4096
#define IN_DIM  1024
#define OUT_DIM 1024
#define NB      8
#define KTOT    (IN_DIM * NB)   // 8192

#define BM 128
#define BN 256
#define BKI 8                  // i per iter -> 64 k
#define KK  (BKI * NB)         // 64
#define NIT (IN_DIM / BKI)     // 128
#define THREADS 256            // 8 warps, 2(M) x 4(N), warp tile 64x64

#define BSCALE 4096.0f
#define INV_BSCALE (1.0f / 4096.0f)

#define A_LD 72                // fp16 per row (144B stride, conflict-free)
#define B_LD 72
#define A_BYTES (BM * A_LD * 2)            // 18432
#define B_BYTES (BN * B_LD * 2)            // 36864
#define BUF_BYTES (A_BYTES + B_BYTES)      // 55296
#define STAGES 3
#define SMEM_DYN (STAGES * BUF_BYTES)      // 165888

// Precomputed fp16 operands. Layouts: [row][k], k = i*8 + d.
__device__ __align__(16) __half gAf[(size_t)BATCH * KTOT];    // 64 MB
__device__ __align__(16) __half gBf[(size_t)OUT_DIM * KTOT];  // 16 MB, x4096

__device__ __forceinline__ void ldx4(uint32_t* r, uint32_t addr) {
    asm volatile("ldmatrix.sync.aligned.m8n8.x4.shared.b16 {%0,%1,%2,%3}, [%4];"
                 : "=r"(r[0]), "=r"(r[1]), "=r"(r[2]), "=r"(r[3]) : "r"(addr));
}
__device__ __forceinline__ void mma16816(float* d, const uint32_t* a, uint32_t b0, uint32_t b1) {
    asm volatile("mma.sync.aligned.m16n8k16.row.col.f32.f16.f16.f32 "
                 "{%0,%1,%2,%3}, {%4,%5,%6,%7}, {%8,%9}, {%0,%1,%2,%3};"
                 : "+f"(d[0]), "+f"(d[1]), "+f"(d[2]), "+f"(d[3])
                 : "r"(a[0]), "r"(a[1]), "r"(a[2]), "r"(a[3]), "r"(b0), "r"(b1));
}
__device__ __forceinline__ void cpa16(uint32_t dst, const void* src) {
    asm volatile("cp.async.cg.shared.global [%0], [%1], 16;" :: "r"(dst), "l"(src));
}
__device__ __forceinline__ uint32_t h2u(__half2 v) {
    return *reinterpret_cast<uint32_t*>(&v);
}

// ---- prep B: coeffs fp32 [i][o][d] -> gBf fp16 [o][i*8+d], scaled ----
__global__ __launch_bounds__(256)
void prep_b_kernel(const float* __restrict__ coeffs) {
    int g = blockIdx.x * 256 + threadIdx.x;   // 0 .. 1048575
    int o = g >> 10;
    int i = g & 1023;
    const float* src = coeffs + ((size_t)i * OUT_DIM + o) * NB;
    float4 v0 = *reinterpret_cast<const float4*>(src);
    float4 v1 = *reinterpret_cast<const float4*>(src + 4);
    __half2 h0 = __floats2half2_rn(v0.x * BSCALE, v0.y * BSCALE);
    __half2 h1 = __floats2half2_rn(v0.z * BSCALE, v0.w * BSCALE);
    __half2 h2 = __floats2half2_rn(v1.x * BSCALE, v1.y * BSCALE);
    __half2 h3 = __floats2half2_rn(v1.z * BSCALE, v1.w * BSCALE);
    *reinterpret_cast<uint4*>(&gBf[(size_t)o * KTOT + (size_t)i * NB]) =
        make_uint4(h2u(h0), h2u(h1), h2u(h2), h2u(h3));
}

// ---- prep A: tanh + recurrence + fp16 -> gAf [m][i*8+d] ----
__global__ __launch_bounds__(256)
void prep_a_kernel(const float* __restrict__ x,
                   const float* __restrict__ a_ptr,
                   const float* __restrict__ q_ptr) {
    int g = blockIdx.x * 256 + threadIdx.x;   // 0 .. 4194303
    int m = g >> 10;
    int i = g & 1023;
    const float a = a_ptr[0];
    const float q = q_ptr[0];
    float xt = tanhf(x[(size_t)m * IN_DIM + i]);
    float p[NB];
    p[0] = 1.0f;
    p[1] = xt - a;
    float qn = q;
#pragma unroll
    for (int n = 2; n < NB; n++) {
        float qn1 = qn * q;
        p[n] = (xt - (a + qn1)) * p[n - 1] - (a * qn) * p[n - 2];
        qn = qn1;
    }
    uint32_t hw[4];
#pragma unroll
    for (int j = 0; j < 4; j++)
        hw[j] = h2u(__floats2half2_rn(p[2 * j], p[2 * j + 1]));
    *reinterpret_cast<uint4*>(&gAf[(size_t)m * KTOT + (size_t)i * NB]) =
        make_uint4(hw[0], hw[1], hw[2], hw[3]);
}

__global__ __launch_bounds__(THREADS, 1)
void kan_v17_kernel(float* __restrict__ y) {
    extern __shared__ __align__(16) char sm[];
    const uint32_t sbase = (uint32_t)__cvta_generic_to_shared(sm);

    const int bn0 = blockIdx.x * BN;
    const int bm0 = blockIdx.y * BM;
    const int tid = threadIdx.x;
    const int lane = tid & 31;
    const int warp = tid >> 5;
    const int wm = warp >> 2;   // 0..1
    const int wn = warp & 3;    // 0..3

    float acc[4][8][4];
#pragma unroll
    for (int mi = 0; mi < 4; mi++)
#pragma unroll
        for (int nb = 0; nb < 8; nb++)
#pragma unroll
            for (int r = 0; r < 4; r++) acc[mi][nb][r] = 0.0f;

    const int aRow = wm * 64 + (lane & 15);
    const uint32_t aOff = (uint32_t)(aRow * A_LD + (lane >> 4) * 8) * 2u;
    const int bRow = wn * 64 + ((lane >> 4) << 3) + (lane & 7);
    const uint32_t bOff = (uint32_t)(bRow * B_LD + ((lane >> 3) & 1) * 8) * 2u;

    auto cpStage = [&](int buf, int it) {
        const uint32_t st = sbase + (uint32_t)buf * BUF_BYTES;
        const int k0 = it * KK;   // 64 k per iter
        // A: 128 rows x 8 chunks = 1024 -> 4 per thread
#pragma unroll
        for (int jj = 0; jj < 4; jj++) {
            int c = tid + jj * THREADS;   // 0..1023
            int row = c >> 3;             // 0..127
            int ch = c & 7;
            const __half* src = gAf + (size_t)(bm0 + row) * KTOT + k0 + ch * 8;
            cpa16(st + (uint32_t)(row * A_LD + ch * 8) * 2u, src);
        }
        // B: 256 rows x 8 chunks = 2048 -> 8 per thread
#pragma unroll
        for (int jj = 0; jj < 8; jj++) {
            int c = tid + jj * THREADS;   // 0..2047
            int row = c >> 3;             // 0..255
            int ch = c & 7;
            const __half* src = gBf + (size_t)(bn0 + row) * KTOT + k0 + ch * 8;
            cpa16(st + A_BYTES + (uint32_t)(row * B_LD + ch * 8) * 2u, src);
        }
        asm volatile("cp.async.commit_group;" ::: "memory");
    };

    auto compute = [&](int buf) {
        const uint32_t base = sbase + (uint32_t)buf * BUF_BYTES;
        const uint32_t pAf = base;
        const uint32_t pBf = base + A_BYTES;
#pragma unroll
        for (int ks = 0; ks < 4; ks++) {       // 4 halves of 16 k
            const uint32_t kb = (uint32_t)ks * 32u;
            uint32_t af[4][4];
#pragma unroll
            for (int mi = 0; mi < 4; mi++)
                ldx4(af[mi], pAf + aOff + kb + (uint32_t)mi * (16 * A_LD * 2));
            uint32_t bc[4], bn_[4];
            ldx4(bc, pBf + bOff + kb);
#pragma unroll
            for (int ng = 0; ng < 4; ng++) {
                if (ng < 3)
                    ldx4(bn_, pBf + bOff + kb + (uint32_t)(ng + 1) * (16 * B_LD * 2));
#pragma unroll
                for (int mi = 0; mi < 4; mi++) {
                    mma16816(acc[mi][2 * ng],     af[mi], bc[0], bc[1]);
                    mma16816(acc[mi][2 * ng + 1], af[mi], bc[2], bc[3]);
                }
                if (ng < 3) {
#pragma unroll
                    for (int t = 0; t < 4; t++) bc[t] = bn_[t];
                }
            }
        }
    };

    // ---- prologue: fill stages 0..1 ----
    cpStage(0, 0);
    cpStage(1, 1);
    asm volatile("cp.async.wait_group 1;" ::: "memory");   // group(0) done
    __syncthreads();

    // ---- main loop: pure cp.async + LDSM + HMMA ----
    for (int it = 0; it < NIT; ++it) {
        compute(it % 3);
        if (it + 1 < NIT) {
            if (it + 2 < NIT) cpStage((it + 2) % 3, it + 2);
            if (it + 2 < NIT) {
                asm volatile("cp.async.wait_group 1;" ::: "memory");
            } else {
                asm volatile("cp.async.wait_group 0;" ::: "memory");
            }
            __syncthreads();
        }
    }

    // ---- epilogue: undo B scale ----
#pragma unroll
    for (int mi = 0; mi < 4; mi++) {
#pragma unroll
        for (int nb = 0; nb < 8; nb++) {
            int r = bm0 + wm * 64 + mi * 16 + (lane >> 2);
            int c = bn0 + wn * 64 + nb * 8 + (lane & 3) * 2;
            *reinterpret_cast<float2*>(y + (size_t)r * OUT_DIM + c) =
                make_float2(acc[mi][nb][0] * INV_BSCALE, acc[mi][nb][1] * INV_BSCALE);
            *reinterpret_cast<float2*>(y + (size_t)(r + 8) * OUT_DIM + c) =
                make_float2(acc[mi][nb][2] * INV_BSCALE, acc[mi][nb][3] * INV_BSCALE);
        }
    }
}

extern "C" void kernel_launch(void* const* d_in, const int* in_sizes, int n_in,
                              void* d_out, int out_size) {
    const float* x      = (const float*)d_in[0];
    const float* a_ptr  = (const float*)d_in[1];
    const float* q_ptr  = (const float*)d_in[2];
    const float* coeffs = (const float*)d_in[3];
    float* y = (float*)d_out;

    prep_b_kernel<<<(OUT_DIM * IN_DIM) / 256, 256>>>(coeffs);
    prep_a_kernel<<<(BATCH * IN_DIM) / 256, 256>>>(x, a_ptr, q_ptr);

    cudaFuncSetAttribute(kan_v17_kernel, cudaFuncAttributeMaxDynamicSharedMemorySize, SMEM_DYN);
    dim3 grid(OUT_DIM / BN, BATCH / BM);  // (4, 32) = 128 CTAs, single wave
    kan_v17_kernel<<<grid, THREADS, SMEM_DYN>>>(y);
}